// round 1
// baseline (speedup 1.0000x reference)
#include <cuda_runtime.h>
#include <math.h>

// ---------------- problem constants ----------------
#define NB    8
#define NC    512
#define NHW   1024
#define NTOK  8192      // NB*NHW
#define ND    512
#define NDC   768
#define NL    77
#define NHEAD 8
#define HDIM  64
#define NFF   2048
#define EPSV  1e-5f

// ---------------- scratch (static device memory; no runtime alloc) ----------
__device__ float g_xn [(size_t)NTOK*ND];
__device__ float g_h  [(size_t)NTOK*ND];
__device__ float g_hn [(size_t)NTOK*ND];
__device__ float g_q  [(size_t)NTOK*ND];
__device__ float g_k  [(size_t)NTOK*ND];
__device__ float g_v  [(size_t)NTOK*ND];
__device__ float g_sim[(size_t)NB*NHEAD*NHW*NHW];   // 256 MB, reused for cross
__device__ float g_ao [(size_t)NTOK*ND];
__device__ float g_ff [(size_t)NTOK*NFF];
__device__ float g_gmean[NB*32];
__device__ float g_grstd[NB*32];

// ---------------- block reduce helper ----------------
__device__ __forceinline__ float blk_reduce(float v, int is_max) {
    __shared__ float sh[33];
    int lane = threadIdx.x & 31, w = threadIdx.x >> 5;
    #pragma unroll
    for (int o = 16; o; o >>= 1) {
        float t = __shfl_down_sync(0xffffffffu, v, o);
        v = is_max ? fmaxf(v, t) : v + t;
    }
    if (!lane) sh[w] = v;
    __syncthreads();
    int nw = blockDim.x >> 5;
    v = (threadIdx.x < nw) ? sh[threadIdx.x] : (is_max ? -1e30f : 0.0f);
    if (w == 0) {
        #pragma unroll
        for (int o = 16; o; o >>= 1) {
            float t = __shfl_down_sync(0xffffffffu, v, o);
            v = is_max ? fmaxf(v, t) : v + t;
        }
        if (threadIdx.x == 0) sh[32] = v;
    }
    __syncthreads();
    float r = sh[32];
    __syncthreads();
    return r;
}

// ---------------- groupnorm stats: one block per (b,g) ----------------
__global__ void gn_stats_k(const float* __restrict__ x, float* __restrict__ mean,
                           float* __restrict__ rstd) {
    int bg = blockIdx.x;                       // 0..255; memory layout is contiguous per group
    const float* p = x + (size_t)bg * 16384;   // 16 ch * 1024 spatial
    float s = 0.f, s2 = 0.f;
    for (int i = threadIdx.x; i < 16384; i += 256) {
        float v = p[i];
        s += v; s2 += v * v;
    }
    s  = blk_reduce(s, 0);
    s2 = blk_reduce(s2, 0);
    if (threadIdx.x == 0) {
        float mu  = s * (1.f / 16384.f);
        float var = s2 * (1.f / 16384.f) - mu * mu;
        mean[bg] = mu;
        rstd[bg] = rsqrtf(var + EPSV);
    }
}

// ---------------- groupnorm apply + transpose [B,C,HW] -> token-major [B,HW,C]
__global__ void gn_apply_k(const float* __restrict__ x, const float* __restrict__ gamma,
                           const float* __restrict__ beta, const float* __restrict__ mean,
                           const float* __restrict__ rstd, float* __restrict__ xn) {
    __shared__ float tile[32][33];
    int b = blockIdx.z;
    int c0 = blockIdx.y * 32, hw0 = blockIdx.x * 32;
    int c = c0 + threadIdx.y, hw = hw0 + threadIdx.x;
    float v = x[((size_t)b * NC + c) * NHW + hw];
    int grp = c >> 4;
    float mu = mean[b * 32 + grp], rs = rstd[b * 32 + grp];
    tile[threadIdx.y][threadIdx.x] = (v - mu) * rs * gamma[c] + beta[c];
    __syncthreads();
    xn[((size_t)b * NHW + hw0 + threadIdx.y) * ND + c0 + threadIdx.x] =
        tile[threadIdx.x][threadIdx.y];
}

// ---------------- layernorm over D=512, one block (256 thr) per row -------
__global__ void ln_k(const float* __restrict__ x, const float* __restrict__ g,
                     const float* __restrict__ b, float* __restrict__ y) {
    size_t row = blockIdx.x;
    const float* xr = x + row * ND;
    float* yr = y + row * ND;
    int t = threadIdx.x;
    float v0 = xr[t], v1 = xr[t + 256];
    float s  = blk_reduce(v0 + v1, 0);
    float s2 = blk_reduce(v0 * v0 + v1 * v1, 0);
    float mu = s * (1.f / ND);
    float rs = rsqrtf(s2 * (1.f / ND) - mu * mu + EPSV);
    yr[t]       = (v0 - mu) * rs * g[t]       + b[t];
    yr[t + 256] = (v1 - mu) * rs * g[t + 256] + b[t + 256];
}

// ---------------- row softmax (scale folded in) ----------------
__global__ void softmax_k(float* __restrict__ s, int cols, float scale) {
    float* row = s + (size_t)blockIdx.x * cols;
    int t = threadIdx.x;
    float m = -1e30f;
    for (int i = t; i < cols; i += 256) m = fmaxf(m, row[i] * scale);
    float mx = blk_reduce(m, 1);
    float sum = 0.f;
    for (int i = t; i < cols; i += 256) {
        float e = __expf(row[i] * scale - mx);
        row[i] = e;
        sum += e;
    }
    float tot = blk_reduce(sum, 0);
    float inv = 1.f / tot;
    for (int i = t; i < cols; i += 256) row[i] *= inv;
}

// ---------------- generic tiled GEMM: C = A @ B (optionally B^T) ---------
// 64x64 block tile, 16x16 threads, 4x4 microtile, K-tile 16.
// Batched via grid.z with decomposed strides: off = (z/bh)*s1 + (z%bh)*s2.
// Epilogue: optional bias (per-col), residual add (same layout as C), exact GELU.
__global__ void gemm_k(const float* __restrict__ A, const float* __restrict__ Bm,
                       float* __restrict__ C,
                       int M, int N, int K, int lda, int ldb, int ldc,
                       int transB, int bh,
                       long long sA1, long long sA2, long long sB1, long long sB2,
                       long long sC1, long long sC2,
                       const float* __restrict__ bias,
                       const float* __restrict__ res,
                       int gelu) {
    int z = blockIdx.z;
    int zb = z / bh, zh = z % bh;
    A  += (long long)zb * sA1 + (long long)zh * sA2;
    Bm += (long long)zb * sB1 + (long long)zh * sB2;
    long long coff = (long long)zb * sC1 + (long long)zh * sC2;
    C += coff;
    if (res) res += coff;

    __shared__ float As[16][68];
    __shared__ float Bs[16][68];

    int tx = threadIdx.x, ty = threadIdx.y;
    int tid = ty * 16 + tx;
    int m0 = blockIdx.y * 64, n0 = blockIdx.x * 64;

    float acc[4][4];
    #pragma unroll
    for (int i = 0; i < 4; i++)
        #pragma unroll
        for (int j = 0; j < 4; j++) acc[i][j] = 0.f;

    for (int k0 = 0; k0 < K; k0 += 16) {
        #pragma unroll
        for (int i = tid; i < 64 * 16; i += 256) {
            int mm = i >> 4, kk = i & 15;
            int gm = m0 + mm, gk = k0 + kk;
            As[kk][mm] = (gm < M && gk < K) ? A[(long long)gm * lda + gk] : 0.f;
        }
        if (transB) {
            #pragma unroll
            for (int i = tid; i < 64 * 16; i += 256) {
                int nn = i >> 4, kk = i & 15;
                int gn = n0 + nn, gk = k0 + kk;
                Bs[kk][nn] = (gn < N && gk < K) ? Bm[(long long)gn * ldb + gk] : 0.f;
            }
        } else {
            #pragma unroll
            for (int i = tid; i < 64 * 16; i += 256) {
                int kk = i >> 6, nn = i & 63;
                int gk = k0 + kk, gn = n0 + nn;
                Bs[kk][nn] = (gk < K && gn < N) ? Bm[(long long)gk * ldb + gn] : 0.f;
            }
        }
        __syncthreads();
        #pragma unroll
        for (int kk = 0; kk < 16; kk++) {
            float a[4], b[4];
            #pragma unroll
            for (int i = 0; i < 4; i++) a[i] = As[kk][ty * 4 + i];
            #pragma unroll
            for (int j = 0; j < 4; j++) b[j] = Bs[kk][tx * 4 + j];
            #pragma unroll
            for (int i = 0; i < 4; i++)
                #pragma unroll
                for (int j = 0; j < 4; j++)
                    acc[i][j] = fmaf(a[i], b[j], acc[i][j]);
        }
        __syncthreads();
    }

    #pragma unroll
    for (int i = 0; i < 4; i++) {
        int gm = m0 + ty * 4 + i;
        if (gm >= M) continue;
        #pragma unroll
        for (int j = 0; j < 4; j++) {
            int gn = n0 + tx * 4 + j;
            if (gn >= N) continue;
            float r = acc[i][j];
            if (bias) r += bias[gn];
            if (res)  r += res[(long long)gm * ldc + gn];
            if (gelu) r = 0.5f * r * (1.f + erff(r * 0.70710678118654752f));
            C[(long long)gm * ldc + gn] = r;
        }
    }
}

// ---------------- final: out[b,c,hw] = t[b,hw,c] + x_in[b,c,hw] -----------
__global__ void out_add_k(const float* __restrict__ t, const float* __restrict__ x_in,
                          float* __restrict__ out) {
    __shared__ float tile[32][33];
    int b = blockIdx.z;
    int c0 = blockIdx.x * 32, hw0 = blockIdx.y * 32;
    tile[threadIdx.y][threadIdx.x] =
        t[((size_t)b * NHW + hw0 + threadIdx.y) * ND + c0 + threadIdx.x];
    __syncthreads();
    size_t o = ((size_t)b * NC + c0 + threadIdx.y) * NHW + hw0 + threadIdx.x;
    out[o] = tile[threadIdx.x][threadIdx.y] + x_in[o];
}

// ---------------- host side ----------------
static void launch_gemm(const float* A, const float* B, float* C,
                        int M, int N, int K, int lda, int ldb, int ldc,
                        int transB, const float* bias, const float* res, int gelu,
                        int batch = 1, int bh = 1,
                        long long sA1 = 0, long long sA2 = 0,
                        long long sB1 = 0, long long sB2 = 0,
                        long long sC1 = 0, long long sC2 = 0) {
    dim3 grid((N + 63) / 64, (M + 63) / 64, batch), block(16, 16);
    gemm_k<<<grid, block>>>(A, B, C, M, N, K, lda, ldb, ldc, transB, bh,
                            sA1, sA2, sB1, sB2, sC1, sC2, bias, res, gelu);
}

extern "C" void kernel_launch(void* const* d_in, const int* in_sizes, int n_in,
                              void* d_out, int out_size) {
    const float* x      = (const float*)d_in[0];
    const float* ctx    = (const float*)d_in[1];
    const float* gn_g   = (const float*)d_in[2];
    const float* gn_b   = (const float*)d_in[3];
    const float* pin_w  = (const float*)d_in[4];
    const float* pin_b  = (const float*)d_in[5];
    const float* ln1_g  = (const float*)d_in[6];
    const float* ln1_b  = (const float*)d_in[7];
    const float* q1_w   = (const float*)d_in[8];
    const float* k1_w   = (const float*)d_in[9];
    const float* v1_w   = (const float*)d_in[10];
    const float* o1_w   = (const float*)d_in[11];
    const float* o1_b   = (const float*)d_in[12];
    const float* ln2_g  = (const float*)d_in[13];
    const float* ln2_b  = (const float*)d_in[14];
    const float* q2_w   = (const float*)d_in[15];
    const float* k2_w   = (const float*)d_in[16];
    const float* v2_w   = (const float*)d_in[17];
    const float* o2_w   = (const float*)d_in[18];
    const float* o2_b   = (const float*)d_in[19];
    const float* ln3_g  = (const float*)d_in[20];
    const float* ln3_b  = (const float*)d_in[21];
    const float* ff1_w  = (const float*)d_in[22];
    const float* ff1_b  = (const float*)d_in[23];
    const float* ff2_w  = (const float*)d_in[24];
    const float* ff2_b  = (const float*)d_in[25];
    const float* pout_w = (const float*)d_in[26];
    const float* pout_b = (const float*)d_in[27];
    float* out = (float*)d_out;

    float *xn, *h, *hn, *q, *k, *v, *sim, *ao, *ff, *gmean, *grstd;
    cudaGetSymbolAddress((void**)&xn,    g_xn);
    cudaGetSymbolAddress((void**)&h,     g_h);
    cudaGetSymbolAddress((void**)&hn,    g_hn);
    cudaGetSymbolAddress((void**)&q,     g_q);
    cudaGetSymbolAddress((void**)&k,     g_k);
    cudaGetSymbolAddress((void**)&v,     g_v);
    cudaGetSymbolAddress((void**)&sim,   g_sim);
    cudaGetSymbolAddress((void**)&ao,    g_ao);
    cudaGetSymbolAddress((void**)&ff,    g_ff);
    cudaGetSymbolAddress((void**)&gmean, g_gmean);
    cudaGetSymbolAddress((void**)&grstd, g_grstd);

    const float scale = 0.125f;   // 1/sqrt(64)

    // 1) GroupNorm + transpose to token-major
    gn_stats_k<<<NB * 32, 256>>>(x, gmean, grstd);
    gn_apply_k<<<dim3(NHW / 32, NC / 32, NB), dim3(32, 32)>>>(x, gn_g, gn_b, gmean, grstd, xn);

    // 2) proj_in: h = xn @ pin_w + pin_b
    launch_gemm(xn, pin_w, h, NTOK, ND, ND, ND, ND, ND, 0, pin_b, nullptr, 0);

    // 3) self-attention
    ln_k<<<NTOK, 256>>>(h, ln1_g, ln1_b, hn);
    launch_gemm(hn, q1_w, q, NTOK, ND, ND, ND, ND, ND, 0, nullptr, nullptr, 0);
    launch_gemm(hn, k1_w, k, NTOK, ND, ND, ND, ND, ND, 0, nullptr, nullptr, 0);
    launch_gemm(hn, v1_w, v, NTOK, ND, ND, ND, ND, ND, 0, nullptr, nullptr, 0);
    // sim[b,h] = q_bh @ k_bh^T     (64 batches of 1024x1024x64)
    launch_gemm(q, k, sim, NHW, NHW, HDIM, ND, ND, NHW, 1, nullptr, nullptr, 0,
                NB * NHEAD, NHEAD,
                (long long)NHW * ND, HDIM,
                (long long)NHW * ND, HDIM,
                (long long)NHEAD * NHW * NHW, (long long)NHW * NHW);
    softmax_k<<<NB * NHEAD * NHW, 256>>>(sim, NHW, scale);
    // ao[b,:,h*64..] = attn @ v_bh   (64 batches of 1024x64x1024)
    launch_gemm(sim, v, ao, NHW, HDIM, NHW, NHW, ND, ND, 0, nullptr, nullptr, 0,
                NB * NHEAD, NHEAD,
                (long long)NHEAD * NHW * NHW, (long long)NHW * NHW,
                (long long)NHW * ND, HDIM,
                (long long)NHW * ND, HDIM);
    // h = ao @ o1_w + o1_b + h
    launch_gemm(ao, o1_w, h, NTOK, ND, ND, ND, ND, ND, 0, o1_b, h, 0);

    // 4) cross-attention
    ln_k<<<NTOK, 256>>>(h, ln2_g, ln2_b, hn);
    launch_gemm(hn, q2_w, q, NTOK, ND, ND, ND, ND, ND, 0, nullptr, nullptr, 0);
    launch_gemm(ctx, k2_w, k, NB * NL, ND, NDC, NDC, ND, ND, 0, nullptr, nullptr, 0);
    launch_gemm(ctx, v2_w, v, NB * NL, ND, NDC, NDC, ND, ND, 0, nullptr, nullptr, 0);
    // sim2[b,h] = q_bh @ k2_bh^T   (64 batches of 1024x77x64)
    launch_gemm(q, k, sim, NHW, NL, HDIM, ND, ND, NL, 1, nullptr, nullptr, 0,
                NB * NHEAD, NHEAD,
                (long long)NHW * ND, HDIM,
                (long long)NL * ND, HDIM,
                (long long)NHEAD * NHW * NL, (long long)NHW * NL);
    softmax_k<<<NB * NHEAD * NHW, 256>>>(sim, NL, scale);
    // ao = attn2 @ v2   (64 batches of 1024x64x77)
    launch_gemm(sim, v, ao, NHW, HDIM, NL, NL, ND, ND, 0, nullptr, nullptr, 0,
                NB * NHEAD, NHEAD,
                (long long)NHEAD * NHW * NL, (long long)NHW * NL,
                (long long)NL * ND, HDIM,
                (long long)NHW * ND, HDIM);
    // h = ao @ o2_w + o2_b + h
    launch_gemm(ao, o2_w, h, NTOK, ND, ND, ND, ND, ND, 0, o2_b, h, 0);

    // 5) feed-forward
    ln_k<<<NTOK, 256>>>(h, ln3_g, ln3_b, hn);
    launch_gemm(hn, ff1_w, ff, NTOK, NFF, ND, ND, NFF, NFF, 0, ff1_b, nullptr, 1);  // gelu
    launch_gemm(ff, ff2_w, h, NTOK, ND, NFF, NFF, ND, ND, 0, ff2_b, h, 0);          // +residual

    // 6) proj_out + input residual
    launch_gemm(h, pout_w, ao, NTOK, NC, ND, ND, NC, NC, 0, pout_b, nullptr, 0);
    out_add_k<<<dim3(NC / 32, NHW / 32, NB), dim3(32, 32)>>>(ao, x, out);
}

// round 2
// speedup vs baseline: 2.6423x; 2.6423x over previous
#include <cuda_runtime.h>
#include <math.h>
#include <stdint.h>

// ---------------- problem constants ----------------
#define NB    8
#define NC    512
#define NHW   1024
#define NTOK  8192      // NB*NHW
#define ND    512
#define NDC   768
#define NL    77
#define NHEAD 8
#define HDIM  64
#define NFF   2048
#define EPSV  1e-5f

// ---------------- scratch (static device memory; no runtime alloc) ----------
__device__ float g_xn [(size_t)NTOK*ND];
__device__ float g_h  [(size_t)NTOK*ND];
__device__ float g_hn [(size_t)NTOK*ND];
__device__ float g_q  [(size_t)NTOK*ND];
__device__ float g_k  [(size_t)NTOK*ND];
__device__ float g_v  [(size_t)NTOK*ND];
__device__ float g_sim[(size_t)NB*NHEAD*NHW*NHW];   // 256 MB, reused for cross
__device__ float g_ao [(size_t)NTOK*ND];
__device__ float g_ff [(size_t)NTOK*NFF];
__device__ float g_gmean[NB*32];
__device__ float g_grstd[NB*32];

// ---------------- block reduce helper ----------------
__device__ __forceinline__ float blk_reduce(float v, int is_max) {
    __shared__ float sh[33];
    int lane = threadIdx.x & 31, w = threadIdx.x >> 5;
    #pragma unroll
    for (int o = 16; o; o >>= 1) {
        float t = __shfl_down_sync(0xffffffffu, v, o);
        v = is_max ? fmaxf(v, t) : v + t;
    }
    if (!lane) sh[w] = v;
    __syncthreads();
    int nw = blockDim.x >> 5;
    v = (threadIdx.x < nw) ? sh[threadIdx.x] : (is_max ? -1e30f : 0.0f);
    if (w == 0) {
        #pragma unroll
        for (int o = 16; o; o >>= 1) {
            float t = __shfl_down_sync(0xffffffffu, v, o);
            v = is_max ? fmaxf(v, t) : v + t;
        }
        if (threadIdx.x == 0) sh[32] = v;
    }
    __syncthreads();
    float r = sh[32];
    __syncthreads();
    return r;
}

// ---------------- groupnorm stats: one block per (b,g) ----------------
__global__ void gn_stats_k(const float* __restrict__ x, float* __restrict__ mean,
                           float* __restrict__ rstd) {
    int bg = blockIdx.x;
    const float* p = x + (size_t)bg * 16384;
    float s = 0.f, s2 = 0.f;
    for (int i = threadIdx.x; i < 16384; i += 256) {
        float v = p[i];
        s += v; s2 += v * v;
    }
    s  = blk_reduce(s, 0);
    s2 = blk_reduce(s2, 0);
    if (threadIdx.x == 0) {
        float mu  = s * (1.f / 16384.f);
        float var = s2 * (1.f / 16384.f) - mu * mu;
        mean[bg] = mu;
        rstd[bg] = rsqrtf(var + EPSV);
    }
}

// ---------------- groupnorm apply + transpose [B,C,HW] -> token-major -----
__global__ void gn_apply_k(const float* __restrict__ x, const float* __restrict__ gamma,
                           const float* __restrict__ beta, const float* __restrict__ mean,
                           const float* __restrict__ rstd, float* __restrict__ xn) {
    __shared__ float tile[32][33];
    int b = blockIdx.z;
    int c0 = blockIdx.y * 32, hw0 = blockIdx.x * 32;
    int c = c0 + threadIdx.y, hw = hw0 + threadIdx.x;
    float v = x[((size_t)b * NC + c) * NHW + hw];
    int grp = c >> 4;
    float mu = mean[b * 32 + grp], rs = rstd[b * 32 + grp];
    tile[threadIdx.y][threadIdx.x] = (v - mu) * rs * gamma[c] + beta[c];
    __syncthreads();
    xn[((size_t)b * NHW + hw0 + threadIdx.y) * ND + c0 + threadIdx.x] =
        tile[threadIdx.x][threadIdx.y];
}

// ---------------- layernorm over D=512 -----------------------------------
__global__ void ln_k(const float* __restrict__ x, const float* __restrict__ g,
                     const float* __restrict__ b, float* __restrict__ y) {
    size_t row = blockIdx.x;
    const float* xr = x + row * ND;
    float* yr = y + row * ND;
    int t = threadIdx.x;
    float v0 = xr[t], v1 = xr[t + 256];
    float s  = blk_reduce(v0 + v1, 0);
    float s2 = blk_reduce(v0 * v0 + v1 * v1, 0);
    float mu = s * (1.f / ND);
    float rs = rsqrtf(s2 * (1.f / ND) - mu * mu + EPSV);
    yr[t]       = (v0 - mu) * rs * g[t]       + b[t];
    yr[t + 256] = (v1 - mu) * rs * g[t + 256] + b[t + 256];
}

// ---------------- softmax over 1024 cols, single pass, registers ----------
__global__ void softmax1024_k(float* __restrict__ s, float scale) {
    float4* row = (float4*)(s + (size_t)blockIdx.x * 1024);
    int t = threadIdx.x;
    float4 v = row[t];
    v.x *= scale; v.y *= scale; v.z *= scale; v.w *= scale;
    float m = fmaxf(fmaxf(v.x, v.y), fmaxf(v.z, v.w));
    float mx = blk_reduce(m, 1);
    v.x = __expf(v.x - mx); v.y = __expf(v.y - mx);
    v.z = __expf(v.z - mx); v.w = __expf(v.w - mx);
    float tot = blk_reduce(v.x + v.y + v.z + v.w, 0);
    float inv = 1.f / tot;
    v.x *= inv; v.y *= inv; v.z *= inv; v.w *= inv;
    row[t] = v;
}

// ---------------- generic strided softmax (cross-attn, cols=77) -----------
__global__ void softmax_k(float* __restrict__ s, int cols, float scale) {
    float* row = s + (size_t)blockIdx.x * cols;
    int t = threadIdx.x;
    float m = -1e30f;
    for (int i = t; i < cols; i += 256) m = fmaxf(m, row[i] * scale);
    float mx = blk_reduce(m, 1);
    float sum = 0.f;
    for (int i = t; i < cols; i += 256) {
        float e = __expf(row[i] * scale - mx);
        row[i] = e;
        sum += e;
    }
    float tot = blk_reduce(sum, 0);
    float inv = 1.f / tot;
    for (int i = t; i < cols; i += 256) row[i] *= inv;
}

// ============ tf32 tensor-core GEMM ========================================
// C = A @ B (optionally B^T), tf32 inputs (rounded), fp32 accumulate.
// Block tile 128x128, K-tile 16, 8 warps: 4(M) x 2(N), warp tile 32x64.
// mma.sync.m16n8k8: per warp 2 M-frags x 8 N-frags.
// Conflict-free smem: A stride 20 words, B stride 136 words (verified).
// Double-buffered, software-pipelined global loads.
// Batched via grid.z: off = (z/bh)*s1 + (z%bh)*s2.
__device__ __forceinline__ uint32_t f2tf32(float f) {
    uint32_t r;
    asm("cvt.rna.tf32.f32 %0, %1;" : "=r"(r) : "f"(f));
    return r;
}

__global__ __launch_bounds__(256, 1)
void mma_gemm_k(const float* __restrict__ A, const float* __restrict__ Bm,
                float* __restrict__ C,
                int M, int N, int K, int lda, int ldb, int ldc,
                int transB, int bh,
                long long sA1, long long sA2, long long sB1, long long sB2,
                long long sC1, long long sC2,
                const float* __restrict__ bias,
                const float* __restrict__ res,
                int gelu) {
    int z = blockIdx.z;
    int zb = z / bh, zh = z % bh;
    A  += (long long)zb * sA1 + (long long)zh * sA2;
    Bm += (long long)zb * sB1 + (long long)zh * sB2;
    long long coff = (long long)zb * sC1 + (long long)zh * sC2;
    C += coff;
    if (res) res += coff;

    __shared__ uint32_t As[2][128][20];   // [m][k], stride 20 words
    __shared__ uint32_t Bs[2][16][136];   // [k][n], stride 136 words

    int tid = threadIdx.x;
    int warp = tid >> 5, lane = tid & 31;
    int wm = warp & 3, wn = warp >> 2;          // 4 x 2 warp grid
    int lr = lane >> 2, lc = lane & 3;          // groupID, threadInGroup
    int m0 = blockIdx.y * 128, n0 = blockIdx.x * 128;

    float acc[2][8][4];
    #pragma unroll
    for (int i = 0; i < 2; i++)
        #pragma unroll
        for (int j = 0; j < 8; j++)
            #pragma unroll
            for (int l = 0; l < 4; l++) acc[i][j][l] = 0.f;

    int KT = (K + 15) >> 4;
    float ra[8], rb[8];

    // prologue: load tile 0
    {
        int k0 = 0;
        #pragma unroll
        for (int i = 0; i < 8; i++) {
            int f = tid + i * 256;
            int row = f >> 4, col = f & 15;
            int gm = m0 + row, gk = k0 + col;
            ra[i] = (gm < M && gk < K) ? A[(long long)gm * lda + gk] : 0.f;
        }
        if (transB) {
            #pragma unroll
            for (int i = 0; i < 8; i++) {
                int f = tid + i * 256;
                int nn = f >> 4, kk = f & 15;
                rb[i] = (n0 + nn < N && k0 + kk < K)
                        ? Bm[(long long)(n0 + nn) * ldb + k0 + kk] : 0.f;
            }
        } else {
            #pragma unroll
            for (int i = 0; i < 8; i++) {
                int f = tid + i * 256;
                int kk = f >> 7, nn = f & 127;
                rb[i] = (k0 + kk < K && n0 + nn < N)
                        ? Bm[(long long)(k0 + kk) * ldb + n0 + nn] : 0.f;
            }
        }
        #pragma unroll
        for (int i = 0; i < 8; i++) {
            int f = tid + i * 256;
            As[0][f >> 4][f & 15] = f2tf32(ra[i]);
        }
        #pragma unroll
        for (int i = 0; i < 8; i++) {
            int f = tid + i * 256;
            if (transB) Bs[0][f & 15][f >> 4] = f2tf32(rb[i]);
            else        Bs[0][f >> 7][f & 127] = f2tf32(rb[i]);
        }
    }
    __syncthreads();

    for (int kt = 0; kt < KT; kt++) {
        int cbuf = kt & 1, nbuf = cbuf ^ 1;
        // prefetch next tile into registers
        if (kt + 1 < KT) {
            int k0 = (kt + 1) << 4;
            #pragma unroll
            for (int i = 0; i < 8; i++) {
                int f = tid + i * 256;
                int row = f >> 4, col = f & 15;
                int gm = m0 + row, gk = k0 + col;
                ra[i] = (gm < M && gk < K) ? A[(long long)gm * lda + gk] : 0.f;
            }
            if (transB) {
                #pragma unroll
                for (int i = 0; i < 8; i++) {
                    int f = tid + i * 256;
                    int nn = f >> 4, kk = f & 15;
                    rb[i] = (n0 + nn < N && k0 + kk < K)
                            ? Bm[(long long)(n0 + nn) * ldb + k0 + kk] : 0.f;
                }
            } else {
                #pragma unroll
                for (int i = 0; i < 8; i++) {
                    int f = tid + i * 256;
                    int kk = f >> 7, nn = f & 127;
                    rb[i] = (k0 + kk < K && n0 + nn < N)
                            ? Bm[(long long)(k0 + kk) * ldb + n0 + nn] : 0.f;
                }
            }
        }
        // compute on current buffer: 2 k-steps of 8
        #pragma unroll
        for (int ks = 0; ks < 16; ks += 8) {
            uint32_t af[2][4];
            #pragma unroll
            for (int mt = 0; mt < 2; mt++) {
                int mr = wm * 32 + mt * 16;
                af[mt][0] = As[cbuf][mr + lr    ][ks + lc    ];
                af[mt][1] = As[cbuf][mr + lr + 8][ks + lc    ];
                af[mt][2] = As[cbuf][mr + lr    ][ks + lc + 4];
                af[mt][3] = As[cbuf][mr + lr + 8][ks + lc + 4];
            }
            uint32_t bf[8][2];
            #pragma unroll
            for (int nt = 0; nt < 8; nt++) {
                int nc = wn * 64 + nt * 8 + lr;
                bf[nt][0] = Bs[cbuf][ks + lc    ][nc];
                bf[nt][1] = Bs[cbuf][ks + lc + 4][nc];
            }
            #pragma unroll
            for (int mt = 0; mt < 2; mt++)
                #pragma unroll
                for (int nt = 0; nt < 8; nt++) {
                    asm volatile(
                        "mma.sync.aligned.m16n8k8.row.col.f32.tf32.tf32.f32 "
                        "{%0,%1,%2,%3}, {%4,%5,%6,%7}, {%8,%9}, {%0,%1,%2,%3};"
                        : "+f"(acc[mt][nt][0]), "+f"(acc[mt][nt][1]),
                          "+f"(acc[mt][nt][2]), "+f"(acc[mt][nt][3])
                        : "r"(af[mt][0]), "r"(af[mt][1]), "r"(af[mt][2]), "r"(af[mt][3]),
                          "r"(bf[nt][0]), "r"(bf[nt][1]));
                }
        }
        // store prefetched tile, flip
        if (kt + 1 < KT) {
            #pragma unroll
            for (int i = 0; i < 8; i++) {
                int f = tid + i * 256;
                As[nbuf][f >> 4][f & 15] = f2tf32(ra[i]);
            }
            #pragma unroll
            for (int i = 0; i < 8; i++) {
                int f = tid + i * 256;
                if (transB) Bs[nbuf][f & 15][f >> 4] = f2tf32(rb[i]);
                else        Bs[nbuf][f >> 7][f & 127] = f2tf32(rb[i]);
            }
            __syncthreads();
        }
    }

    // epilogue
    #pragma unroll
    for (int mt = 0; mt < 2; mt++) {
        #pragma unroll
        for (int nt = 0; nt < 8; nt++) {
            int row0 = m0 + wm * 32 + mt * 16 + lr;
            int col0 = n0 + wn * 64 + nt * 8 + 2 * lc;
            #pragma unroll
            for (int half = 0; half < 2; half++) {
                int gm = row0 + half * 8;
                if (gm >= M) continue;
                #pragma unroll
                for (int j = 0; j < 2; j++) {
                    int gn = col0 + j;
                    if (gn >= N) continue;
                    float r = acc[mt][nt][half * 2 + j];
                    if (bias) r += bias[gn];
                    if (res)  r += res[(long long)gm * ldc + gn];
                    if (gelu) r = 0.5f * r * (1.f + erff(r * 0.70710678118654752f));
                    C[(long long)gm * ldc + gn] = r;
                }
            }
        }
    }
}

// ---------------- final: out[b,c,hw] = t[b,hw,c] + x_in[b,c,hw] -----------
__global__ void out_add_k(const float* __restrict__ t, const float* __restrict__ x_in,
                          float* __restrict__ out) {
    __shared__ float tile[32][33];
    int b = blockIdx.z;
    int c0 = blockIdx.x * 32, hw0 = blockIdx.y * 32;
    tile[threadIdx.y][threadIdx.x] =
        t[((size_t)b * NHW + hw0 + threadIdx.y) * ND + c0 + threadIdx.x];
    __syncthreads();
    size_t o = ((size_t)b * NC + c0 + threadIdx.y) * NHW + hw0 + threadIdx.x;
    out[o] = tile[threadIdx.x][threadIdx.y] + x_in[o];
}

// ---------------- host side ----------------
static void launch_gemm(const float* A, const float* B, float* C,
                        int M, int N, int K, int lda, int ldb, int ldc,
                        int transB, const float* bias, const float* res, int gelu,
                        int batch = 1, int bh = 1,
                        long long sA1 = 0, long long sA2 = 0,
                        long long sB1 = 0, long long sB2 = 0,
                        long long sC1 = 0, long long sC2 = 0) {
    dim3 grid((N + 127) / 128, (M + 127) / 128, batch);
    mma_gemm_k<<<grid, 256>>>(A, B, C, M, N, K, lda, ldb, ldc, transB, bh,
                              sA1, sA2, sB1, sB2, sC1, sC2, bias, res, gelu);
}

extern "C" void kernel_launch(void* const* d_in, const int* in_sizes, int n_in,
                              void* d_out, int out_size) {
    const float* x      = (const float*)d_in[0];
    const float* ctx    = (const float*)d_in[1];
    const float* gn_g   = (const float*)d_in[2];
    const float* gn_b   = (const float*)d_in[3];
    const float* pin_w  = (const float*)d_in[4];
    const float* pin_b  = (const float*)d_in[5];
    const float* ln1_g  = (const float*)d_in[6];
    const float* ln1_b  = (const float*)d_in[7];
    const float* q1_w   = (const float*)d_in[8];
    const float* k1_w   = (const float*)d_in[9];
    const float* v1_w   = (const float*)d_in[10];
    const float* o1_w   = (const float*)d_in[11];
    const float* o1_b   = (const float*)d_in[12];
    const float* ln2_g  = (const float*)d_in[13];
    const float* ln2_b  = (const float*)d_in[14];
    const float* q2_w   = (const float*)d_in[15];
    const float* k2_w   = (const float*)d_in[16];
    const float* v2_w   = (const float*)d_in[17];
    const float* o2_w   = (const float*)d_in[18];
    const float* o2_b   = (const float*)d_in[19];
    const float* ln3_g  = (const float*)d_in[20];
    const float* ln3_b  = (const float*)d_in[21];
    const float* ff1_w  = (const float*)d_in[22];
    const float* ff1_b  = (const float*)d_in[23];
    const float* ff2_w  = (const float*)d_in[24];
    const float* ff2_b  = (const float*)d_in[25];
    const float* pout_w = (const float*)d_in[26];
    const float* pout_b = (const float*)d_in[27];
    float* out = (float*)d_out;

    float *xn, *h, *hn, *q, *k, *v, *sim, *ao, *ff, *gmean, *grstd;
    cudaGetSymbolAddress((void**)&xn,    g_xn);
    cudaGetSymbolAddress((void**)&h,     g_h);
    cudaGetSymbolAddress((void**)&hn,    g_hn);
    cudaGetSymbolAddress((void**)&q,     g_q);
    cudaGetSymbolAddress((void**)&k,     g_k);
    cudaGetSymbolAddress((void**)&v,     g_v);
    cudaGetSymbolAddress((void**)&sim,   g_sim);
    cudaGetSymbolAddress((void**)&ao,    g_ao);
    cudaGetSymbolAddress((void**)&ff,    g_ff);
    cudaGetSymbolAddress((void**)&gmean, g_gmean);
    cudaGetSymbolAddress((void**)&grstd, g_grstd);

    const float scale = 0.125f;   // 1/sqrt(64)

    // 1) GroupNorm + transpose to token-major
    gn_stats_k<<<NB * 32, 256>>>(x, gmean, grstd);
    gn_apply_k<<<dim3(NHW / 32, NC / 32, NB), dim3(32, 32)>>>(x, gn_g, gn_b, gmean, grstd, xn);

    // 2) proj_in
    launch_gemm(xn, pin_w, h, NTOK, ND, ND, ND, ND, ND, 0, pin_b, nullptr, 0);

    // 3) self-attention
    ln_k<<<NTOK, 256>>>(h, ln1_g, ln1_b, hn);
    launch_gemm(hn, q1_w, q, NTOK, ND, ND, ND, ND, ND, 0, nullptr, nullptr, 0);
    launch_gemm(hn, k1_w, k, NTOK, ND, ND, ND, ND, ND, 0, nullptr, nullptr, 0);
    launch_gemm(hn, v1_w, v, NTOK, ND, ND, ND, ND, ND, 0, nullptr, nullptr, 0);
    // sim[b,h] = q_bh @ k_bh^T   (64 batches of 1024x1024x64)
    launch_gemm(q, k, sim, NHW, NHW, HDIM, ND, ND, NHW, 1, nullptr, nullptr, 0,
                NB * NHEAD, NHEAD,
                (long long)NHW * ND, HDIM,
                (long long)NHW * ND, HDIM,
                (long long)NHEAD * NHW * NHW, (long long)NHW * NHW);
    softmax1024_k<<<NB * NHEAD * NHW, 256>>>(sim, scale);
    // ao = attn @ v   (64 batches of 1024x64x1024)
    launch_gemm(sim, v, ao, NHW, HDIM, NHW, NHW, ND, ND, 0, nullptr, nullptr, 0,
                NB * NHEAD, NHEAD,
                (long long)NHEAD * NHW * NHW, (long long)NHW * NHW,
                (long long)NHW * ND, HDIM,
                (long long)NHW * ND, HDIM);
    launch_gemm(ao, o1_w, h, NTOK, ND, ND, ND, ND, ND, 0, o1_b, h, 0);

    // 4) cross-attention
    ln_k<<<NTOK, 256>>>(h, ln2_g, ln2_b, hn);
    launch_gemm(hn, q2_w, q, NTOK, ND, ND, ND, ND, ND, 0, nullptr, nullptr, 0);
    launch_gemm(ctx, k2_w, k, NB * NL, ND, NDC, NDC, ND, ND, 0, nullptr, nullptr, 0);
    launch_gemm(ctx, v2_w, v, NB * NL, ND, NDC, NDC, ND, ND, 0, nullptr, nullptr, 0);
    // sim2[b,h] = q_bh @ k2_bh^T   (64 batches of 1024x77x64)
    launch_gemm(q, k, sim, NHW, NL, HDIM, ND, ND, NL, 1, nullptr, nullptr, 0,
                NB * NHEAD, NHEAD,
                (long long)NHW * ND, HDIM,
                (long long)NL * ND, HDIM,
                (long long)NHEAD * NHW * NL, (long long)NHW * NL);
    softmax_k<<<NB * NHEAD * NHW, 256>>>(sim, NL, scale);
    // ao = attn2 @ v2   (64 batches of 1024x64x77)
    launch_gemm(sim, v, ao, NHW, HDIM, NL, NL, ND, ND, 0, nullptr, nullptr, 0,
                NB * NHEAD, NHEAD,
                (long long)NHEAD * NHW * NL, (long long)NHW * NL,
                (long long)NL * ND, HDIM,
                (long long)NHW * ND, HDIM);
    launch_gemm(ao, o2_w, h, NTOK, ND, ND, ND, ND, ND, 0, o2_b, h, 0);

    // 5) feed-forward
    ln_k<<<NTOK, 256>>>(h, ln3_g, ln3_b, hn);
    launch_gemm(hn, ff1_w, ff, NTOK, NFF, ND, ND, NFF, NFF, 0, ff1_b, nullptr, 1);
    launch_gemm(ff, ff2_w, h, NTOK, ND, NFF, NFF, ND, ND, 0, ff2_b, h, 0);

    // 6) proj_out + input residual
    launch_gemm(h, pout_w, ao, NTOK, NC, ND, ND, NC, NC, 0, pout_b, nullptr, 0);
    out_add_k<<<dim3(NC / 32, NHW / 32, NB), dim3(32, 32)>>>(ao, x, out);
}

// round 4
// speedup vs baseline: 5.0464x; 1.9099x over previous
#include <cuda_runtime.h>
#include <math.h>
#include <stdint.h>

// ---------------- problem constants ----------------
#define NB    8
#define NC    512
#define NHW   1024
#define NTOK  8192
#define ND    512
#define NDC   768
#define NL    77
#define NLP   96      // padded cross length (16B-aligned rows)
#define NHEAD 8
#define HDIM  64
#define NFF   2048
#define EPSV  1e-5f

// ---------------- scratch ----------------
__device__ float g_xn [(size_t)NTOK*ND];
__device__ float g_h  [(size_t)NTOK*ND];
__device__ float g_hn [(size_t)NTOK*ND];
__device__ float g_q  [(size_t)NTOK*ND];
__device__ float g_k  [(size_t)NTOK*ND];
__device__ float g_v  [(size_t)NTOK*ND];
__device__ float g_sim[(size_t)NB*NHEAD*NHW*NHW];
__device__ float g_ao [(size_t)NTOK*ND];
__device__ float g_ff [(size_t)NTOK*NFF];
__device__ float g_gmean[NB*32];
__device__ float g_grstd[NB*32];

// ---------------- PTX helpers ----------------
__device__ __forceinline__ uint32_t smem_u32(const void* p) {
    uint32_t a;
    asm("{ .reg .u64 t; cvta.to.shared.u64 t, %1; cvt.u32.u64 %0, t; }" : "=r"(a) : "l"(p));
    return a;
}
__device__ __forceinline__ void cp16(uint32_t dst, const void* src, bool pred) {
    int sz = pred ? 16 : 0;
    asm volatile("cp.async.cg.shared.global [%0], [%1], 16, %2;\n" :: "r"(dst), "l"(src), "r"(sz));
}

// ================= tf32 warp-MMA GEMM, cp.async 3-stage pipeline ==========
// C[M,N] = A[M,K] @ B  (TRANSB: B is [N,K] K-major; else B is [K,N] N-major)
// Block tile 128 x BN, K-tile 32, 256 threads (8 warps, 4(M) x 2(N)).
// Warp tile 32 x BN/2, m16n8k8 tf32 HMMA, raw-fp32 operands (HW truncation).
template<int BN, bool TRANSB>
__global__ __launch_bounds__(256)
void mma_gemm_k(const float* __restrict__ A, const float* __restrict__ Bm,
                float* __restrict__ C,
                int M, int N, int K, int lda, int ldb, int ldc, int bh,
                long long sA1, long long sA2, long long sB1, long long sB2,
                long long sC1, long long sC2,
                const float* __restrict__ bias,
                const float* __restrict__ res,
                int gelu) {
    constexpr int SA = 36;                       // A smem row stride (words)
    constexpr int SB = TRANSB ? 36 : (BN + 8);   // B smem row stride (words)
    constexpr int AW = 128 * SA;
    constexpr int BW = TRANSB ? BN * 36 : 32 * (BN + 8);
    constexpr int STW = AW + BW;                 // words per stage
    constexpr int WN = BN / 2;                   // warp N extent
    constexpr int NF = WN / 8;                   // N frags per warp

    extern __shared__ float sm[];

    int z = blockIdx.z, zb = z / bh, zh = z - zb * bh;
    A  += (long long)zb * sA1 + (long long)zh * sA2;
    Bm += (long long)zb * sB1 + (long long)zh * sB2;
    long long coff = (long long)zb * sC1 + (long long)zh * sC2;
    C += coff;
    if (res) res += coff;

    int tid = threadIdx.x;
    int warp = tid >> 5, lane = tid & 31;
    int wm = warp & 3, wn = warp >> 2;
    int lr = lane >> 2, lc = lane & 3;
    int m0 = blockIdx.y * 128, n0 = blockIdx.x * BN;

    float acc[2][NF][4];
    #pragma unroll
    for (int i = 0; i < 2; i++)
        #pragma unroll
        for (int j = 0; j < NF; j++)
            #pragma unroll
            for (int l = 0; l < 4; l++) acc[i][j][l] = 0.f;

    int KT = K >> 5;

    auto load_tile = [&](int st, int kt) {
        float* As = sm + st * STW;
        float* Bs = As + AW;
        int k0 = kt << 5;
        #pragma unroll
        for (int i = 0; i < 4; i++) {                 // A: 128 rows x 8 chunks
            int idx = tid + i * 256;
            int m = idx >> 3, c = idx & 7;
            int gm = m0 + m;
            int gs = gm < M ? gm : M - 1;
            cp16(smem_u32(&As[m * SA + c * 4]),
                 A + (long long)gs * lda + k0 + c * 4, gm < M);
        }
        if (TRANSB) {
            #pragma unroll
            for (int i = 0; i < BN / 32; i++) {       // B: BN rows x 8 chunks
                int idx = tid + i * 256;
                int n = idx >> 3, c = idx & 7;
                int gn = n0 + n;
                int gs = gn < N ? gn : N - 1;
                cp16(smem_u32(&Bs[n * SB + c * 4]),
                     Bm + (long long)gs * ldb + k0 + c * 4, gn < N);
            }
        } else {
            constexpr int CPB = BN / 4;               // chunks per k-row
            #pragma unroll
            for (int i = 0; i < BN / 32; i++) {       // B: 32 rows x CPB chunks
                int idx = tid + i * 256;
                int kk = idx / CPB, c = idx % CPB;
                cp16(smem_u32(&Bs[kk * SB + c * 4]),
                     Bm + (long long)(k0 + kk) * ldb + n0 + c * 4, true);
            }
        }
        asm volatile("cp.async.commit_group;\n" ::: "memory");
    };

    load_tile(0, 0);
    load_tile(1 % 3, 1 < KT ? 1 : 0);   // KT >= 2 for all our shapes anyway

    for (int kt = 0; kt < KT; kt++) {
        if (kt + 1 < KT) { asm volatile("cp.async.wait_group 1;\n" ::: "memory"); }
        else             { asm volatile("cp.async.wait_group 0;\n" ::: "memory"); }
        __syncthreads();
        if (kt + 2 < KT) load_tile((kt + 2) % 3, kt + 2);

        const float* As = sm + (kt % 3) * STW;
        const float* Bs = As + AW;
        #pragma unroll
        for (int ks4 = 0; ks4 < 4; ks4++) {
            int ks = ks4 * 8;
            uint32_t af[2][4];
            #pragma unroll
            for (int mt = 0; mt < 2; mt++) {
                int mr = wm * 32 + mt * 16;
                af[mt][0] = __float_as_uint(As[(mr + lr    ) * SA + ks + lc    ]);
                af[mt][1] = __float_as_uint(As[(mr + lr + 8) * SA + ks + lc    ]);
                af[mt][2] = __float_as_uint(As[(mr + lr    ) * SA + ks + lc + 4]);
                af[mt][3] = __float_as_uint(As[(mr + lr + 8) * SA + ks + lc + 4]);
            }
            uint32_t bf[NF][2];
            #pragma unroll
            for (int nt = 0; nt < NF; nt++) {
                int nc = wn * WN + nt * 8 + lr;
                if (TRANSB) {
                    bf[nt][0] = __float_as_uint(Bs[nc * SB + ks + lc    ]);
                    bf[nt][1] = __float_as_uint(Bs[nc * SB + ks + lc + 4]);
                } else {
                    bf[nt][0] = __float_as_uint(Bs[(ks + lc    ) * SB + nc]);
                    bf[nt][1] = __float_as_uint(Bs[(ks + lc + 4) * SB + nc]);
                }
            }
            #pragma unroll
            for (int mt = 0; mt < 2; mt++)
                #pragma unroll
                for (int nt = 0; nt < NF; nt++) {
                    asm volatile(
                        "mma.sync.aligned.m16n8k8.row.col.f32.tf32.tf32.f32 "
                        "{%0,%1,%2,%3}, {%4,%5,%6,%7}, {%8,%9}, {%0,%1,%2,%3};"
                        : "+f"(acc[mt][nt][0]), "+f"(acc[mt][nt][1]),
                          "+f"(acc[mt][nt][2]), "+f"(acc[mt][nt][3])
                        : "r"(af[mt][0]), "r"(af[mt][1]), "r"(af[mt][2]), "r"(af[mt][3]),
                          "r"(bf[nt][0]), "r"(bf[nt][1]));
                }
        }
    }

    // epilogue
    #pragma unroll
    for (int mt = 0; mt < 2; mt++) {
        #pragma unroll
        for (int nt = 0; nt < NF; nt++) {
            int row0 = m0 + wm * 32 + mt * 16 + lr;
            int col0 = n0 + wn * WN + nt * 8 + 2 * lc;
            #pragma unroll
            for (int half = 0; half < 2; half++) {
                int gm = row0 + half * 8;
                if (gm >= M) continue;
                #pragma unroll
                for (int j = 0; j < 2; j++) {
                    int gn = col0 + j;
                    if (gn >= N) continue;
                    float r = acc[mt][nt][half * 2 + j];
                    if (bias) r += bias[gn];
                    if (res)  r += res[(long long)gm * ldc + gn];
                    if (gelu) r = 0.5f * r * (1.f + erff(r * 0.70710678118654752f));
                    C[(long long)gm * ldc + gn] = r;
                }
            }
        }
    }
}

// ================= small kernels =================
__device__ __forceinline__ float blk_reduce(float v, int is_max) {
    __shared__ float sh[33];
    int lane = threadIdx.x & 31, w = threadIdx.x >> 5;
    #pragma unroll
    for (int o = 16; o; o >>= 1) {
        float t = __shfl_down_sync(0xffffffffu, v, o);
        v = is_max ? fmaxf(v, t) : v + t;
    }
    if (!lane) sh[w] = v;
    __syncthreads();
    int nw = blockDim.x >> 5;
    v = (threadIdx.x < nw) ? sh[threadIdx.x] : (is_max ? -1e30f : 0.0f);
    if (w == 0) {
        #pragma unroll
        for (int o = 16; o; o >>= 1) {
            float t = __shfl_down_sync(0xffffffffu, v, o);
            v = is_max ? fmaxf(v, t) : v + t;
        }
        if (threadIdx.x == 0) sh[32] = v;
    }
    __syncthreads();
    float r = sh[32];
    __syncthreads();
    return r;
}

__global__ void gn_stats_k(const float* __restrict__ x, float* __restrict__ mean,
                           float* __restrict__ rstd) {
    int bg = blockIdx.x;
    const float* p = x + (size_t)bg * 16384;
    float s = 0.f, s2 = 0.f;
    for (int i = threadIdx.x; i < 16384; i += 256) {
        float v = p[i];
        s += v; s2 += v * v;
    }
    s  = blk_reduce(s, 0);
    s2 = blk_reduce(s2, 0);
    if (threadIdx.x == 0) {
        float mu  = s * (1.f / 16384.f);
        float var = s2 * (1.f / 16384.f) - mu * mu;
        mean[bg] = mu;
        rstd[bg] = rsqrtf(var + EPSV);
    }
}

__global__ void gn_apply_k(const float* __restrict__ x, const float* __restrict__ gamma,
                           const float* __restrict__ beta, const float* __restrict__ mean,
                           const float* __restrict__ rstd, float* __restrict__ xn) {
    __shared__ float tile[32][33];
    int b = blockIdx.z;
    int c0 = blockIdx.y * 32, hw0 = blockIdx.x * 32;
    int c = c0 + threadIdx.y, hw = hw0 + threadIdx.x;
    float v = x[((size_t)b * NC + c) * NHW + hw];
    int grp = c >> 4;
    float mu = mean[b * 32 + grp], rs = rstd[b * 32 + grp];
    tile[threadIdx.y][threadIdx.x] = (v - mu) * rs * gamma[c] + beta[c];
    __syncthreads();
    xn[((size_t)b * NHW + hw0 + threadIdx.y) * ND + c0 + threadIdx.x] =
        tile[threadIdx.x][threadIdx.y];
}

__global__ void ln_k(const float* __restrict__ x, const float* __restrict__ g,
                     const float* __restrict__ b, float* __restrict__ y) {
    size_t row = blockIdx.x;
    const float* xr = x + row * ND;
    float* yr = y + row * ND;
    int t = threadIdx.x;
    float v0 = xr[t], v1 = xr[t + 256];
    float s  = blk_reduce(v0 + v1, 0);
    float s2 = blk_reduce(v0 * v0 + v1 * v1, 0);
    float mu = s * (1.f / ND);
    float rs = rsqrtf(s2 * (1.f / ND) - mu * mu + EPSV);
    yr[t]       = (v0 - mu) * rs * g[t]       + b[t];
    yr[t + 256] = (v1 - mu) * rs * g[t + 256] + b[t + 256];
}

__global__ void softmax1024_k(float* __restrict__ s, float scale) {
    float4* row = (float4*)(s + (size_t)blockIdx.x * 1024);
    int t = threadIdx.x;
    float4 v = row[t];
    v.x *= scale; v.y *= scale; v.z *= scale; v.w *= scale;
    float m = fmaxf(fmaxf(v.x, v.y), fmaxf(v.z, v.w));
    float mx = blk_reduce(m, 1);
    v.x = __expf(v.x - mx); v.y = __expf(v.y - mx);
    v.z = __expf(v.z - mx); v.w = __expf(v.w - mx);
    float tot = blk_reduce(v.x + v.y + v.z + v.w, 0);
    float inv = 1.f / tot;
    v.x *= inv; v.y *= inv; v.z *= inv; v.w *= inv;
    row[t] = v;
}

// cross softmax: rows of stride 96, valid cols 77, zero the pad
__global__ void softmax_cross_k(float* __restrict__ s, float scale) {
    int row = blockIdx.x * 8 + (threadIdx.x >> 5);
    int lane = threadIdx.x & 31;
    float* p = s + (size_t)row * NLP;
    float a0 = p[lane] * scale;
    float a1 = (lane + 32 < NL) ? p[lane + 32] * scale : -1e30f;
    float a2 = (lane + 64 < NL) ? p[lane + 64] * scale : -1e30f;
    float m = fmaxf(a0, fmaxf(a1, a2));
    #pragma unroll
    for (int o = 16; o; o >>= 1) m = fmaxf(m, __shfl_xor_sync(0xffffffffu, m, o));
    float e0 = __expf(a0 - m);
    float e1 = (lane + 32 < NL) ? __expf(a1 - m) : 0.f;
    float e2 = (lane + 64 < NL) ? __expf(a2 - m) : 0.f;
    float t = e0 + e1 + e2;
    #pragma unroll
    for (int o = 16; o; o >>= 1) t += __shfl_xor_sync(0xffffffffu, t, o);
    float inv = 1.f / t;
    p[lane] = e0 * inv;
    p[lane + 32] = (lane + 32 < NL) ? e1 * inv : 0.f;
    p[lane + 64] = (lane + 64 < NL) ? e2 * inv : 0.f;
}

__global__ void out_add_k(const float* __restrict__ t, const float* __restrict__ x_in,
                          float* __restrict__ out) {
    __shared__ float tile[32][33];
    int b = blockIdx.z;
    int c0 = blockIdx.x * 32, hw0 = blockIdx.y * 32;
    tile[threadIdx.y][threadIdx.x] =
        t[((size_t)b * NHW + hw0 + threadIdx.y) * ND + c0 + threadIdx.x];
    __syncthreads();
    size_t o = ((size_t)b * NC + c0 + threadIdx.y) * NHW + hw0 + threadIdx.x;
    out[o] = tile[threadIdx.x][threadIdx.y] + x_in[o];
}

// ================= host =================
template<int BN, bool TRANSB>
static void tcl(const float* A, const float* B, float* C,
                int M, int N, int K, int lda, int ldb, int ldc,
                const float* bias, const float* res, int gelu,
                int batch = 1, int bh = 1,
                long long sA1 = 0, long long sA2 = 0,
                long long sB1 = 0, long long sB2 = 0,
                long long sC1 = 0, long long sC2 = 0) {
    constexpr int AW = 128 * 36;
    constexpr int BW = TRANSB ? BN * 36 : 32 * (BN + 8);
    int smem = 3 * (AW + BW) * 4;
    static bool attr_set = false;
    if (!attr_set) {
        cudaFuncSetAttribute(mma_gemm_k<BN, TRANSB>,
                             cudaFuncAttributeMaxDynamicSharedMemorySize, smem);
        attr_set = true;
    }
    dim3 grid((N + BN - 1) / BN, (M + 127) / 128, batch);
    mma_gemm_k<BN, TRANSB><<<grid, 256, smem>>>(A, B, C, M, N, K, lda, ldb, ldc, bh,
                                                sA1, sA2, sB1, sB2, sC1, sC2,
                                                bias, res, gelu);
}

extern "C" void kernel_launch(void* const* d_in, const int* in_sizes, int n_in,
                              void* d_out, int out_size) {
    const float* x      = (const float*)d_in[0];
    const float* ctx    = (const float*)d_in[1];
    const float* gn_g   = (const float*)d_in[2];
    const float* gn_b   = (const float*)d_in[3];
    const float* pin_w  = (const float*)d_in[4];
    const float* pin_b  = (const float*)d_in[5];
    const float* ln1_g  = (const float*)d_in[6];
    const float* ln1_b  = (const float*)d_in[7];
    const float* q1_w   = (const float*)d_in[8];
    const float* k1_w   = (const float*)d_in[9];
    const float* v1_w   = (const float*)d_in[10];
    const float* o1_w   = (const float*)d_in[11];
    const float* o1_b   = (const float*)d_in[12];
    const float* ln2_g  = (const float*)d_in[13];
    const float* ln2_b  = (const float*)d_in[14];
    const float* q2_w   = (const float*)d_in[15];
    const float* k2_w   = (const float*)d_in[16];
    const float* v2_w   = (const float*)d_in[17];
    const float* o2_w   = (const float*)d_in[18];
    const float* o2_b   = (const float*)d_in[19];
    const float* ln3_g  = (const float*)d_in[20];
    const float* ln3_b  = (const float*)d_in[21];
    const float* ff1_w  = (const float*)d_in[22];
    const float* ff1_b  = (const float*)d_in[23];
    const float* ff2_w  = (const float*)d_in[24];
    const float* ff2_b  = (const float*)d_in[25];
    const float* pout_w = (const float*)d_in[26];
    const float* pout_b = (const float*)d_in[27];
    float* out = (float*)d_out;

    float *xn, *h, *hn, *q, *k, *v, *sim, *ao, *ff, *gmean, *grstd;
    cudaGetSymbolAddress((void**)&xn,    g_xn);
    cudaGetSymbolAddress((void**)&h,     g_h);
    cudaGetSymbolAddress((void**)&hn,    g_hn);
    cudaGetSymbolAddress((void**)&q,     g_q);
    cudaGetSymbolAddress((void**)&k,     g_k);
    cudaGetSymbolAddress((void**)&v,     g_v);
    cudaGetSymbolAddress((void**)&sim,   g_sim);
    cudaGetSymbolAddress((void**)&ao,    g_ao);
    cudaGetSymbolAddress((void**)&ff,    g_ff);
    cudaGetSymbolAddress((void**)&gmean, g_gmean);
    cudaGetSymbolAddress((void**)&grstd, g_grstd);

    const float scale = 0.125f;
    dim3 t32(32, 32);

    // 1) GroupNorm + transpose to token-major
    gn_stats_k<<<NB * 32, 256>>>(x, gmean, grstd);
    gn_apply_k<<<dim3(NHW / 32, NC / 32, NB), t32>>>(x, gn_g, gn_b, gmean, grstd, xn);

    // 2) proj_in
    tcl<128, false>(xn, pin_w, h, NTOK, ND, ND, ND, ND, ND, pin_b, nullptr, 0);

    // 3) self-attention
    ln_k<<<NTOK, 256>>>(h, ln1_g, ln1_b, hn);
    tcl<128, false>(hn, q1_w, q, NTOK, ND, ND, ND, ND, ND, nullptr, nullptr, 0);
    tcl<128, false>(hn, k1_w, k, NTOK, ND, ND, ND, ND, ND, nullptr, nullptr, 0);
    tcl<128, false>(hn, v1_w, v, NTOK, ND, ND, ND, ND, ND, nullptr, nullptr, 0);
    // sim = q @ k^T per (b,h)   (64 batches, 1024x1024x64, B K-major)
    tcl<128, true>(q, k, sim, NHW, NHW, HDIM, ND, ND, NHW, nullptr, nullptr, 0,
                   NB * NHEAD, NHEAD,
                   (long long)NHW * ND, HDIM,
                   (long long)NHW * ND, HDIM,
                   (long long)NHEAD * NHW * NHW, (long long)NHW * NHW);
    softmax1024_k<<<NB * NHEAD * NHW, 256>>>(sim, scale);
    // ao = attn @ v   (64 batches, 1024x64x1024, B = v slice, N-major)
    tcl<64, false>(sim, v, ao, NHW, HDIM, NHW, NHW, ND, ND, nullptr, nullptr, 0,
                   NB * NHEAD, NHEAD,
                   (long long)NHEAD * NHW * NHW, (long long)NHW * NHW,
                   (long long)NHW * ND, HDIM,
                   (long long)NHW * ND, HDIM);
    tcl<128, false>(ao, o1_w, h, NTOK, ND, ND, ND, ND, ND, o1_b, h, 0);

    // 4) cross-attention
    ln_k<<<NTOK, 256>>>(h, ln2_g, ln2_b, hn);
    tcl<128, false>(hn, q2_w, q, NTOK, ND, ND, ND, ND, ND, nullptr, nullptr, 0);
    tcl<128, false>(ctx, k2_w, k, NB * NL, ND, NDC, NDC, ND, ND, nullptr, nullptr, 0);
    tcl<128, false>(ctx, v2_w, v, NB * NL, ND, NDC, NDC, ND, ND, nullptr, nullptr, 0);
    // sim2 = q @ k2^T   (cols padded to 96; pad cols get junk, softmax zeroes them)
    tcl<128, true>(q, k, sim, NHW, NLP, HDIM, ND, ND, NLP, nullptr, nullptr, 0,
                   NB * NHEAD, NHEAD,
                   (long long)NHW * ND, HDIM,
                   (long long)NL * ND, HDIM,
                   (long long)NHEAD * NHW * NLP, (long long)NHW * NLP);
    softmax_cross_k<<<NB * NHEAD * NHW / 8, 256>>>(sim, scale);
    // ao = attn2 @ v2   (K=96: A pad cols are exact zeros; B rows 77..95 junk x 0)
    tcl<64, false>(sim, v, ao, NHW, HDIM, NLP, NLP, ND, ND, nullptr, nullptr, 0,
                   NB * NHEAD, NHEAD,
                   (long long)NHEAD * NHW * NLP, (long long)NHW * NLP,
                   (long long)NL * ND, HDIM,
                   (long long)NHW * ND, HDIM);
    tcl<128, false>(ao, o2_w, h, NTOK, ND, ND, ND, ND, ND, o2_b, h, 0);

    // 5) feed-forward
    ln_k<<<NTOK, 256>>>(h, ln3_g, ln3_b, hn);
    tcl<128, false>(hn, ff1_w, ff, NTOK, NFF, ND, ND, NFF, NFF, ff1_b, nullptr, 1);
    tcl<128, false>(ff, ff2_w, h, NTOK, ND, NFF, NFF, ND, ND, ff2_b, h, 0);

    // 6) proj_out + input residual
    tcl<128, false>(h, pout_w, ao, NTOK, NC, ND, ND, NC, NC, pout_b, nullptr, 0);
    out_add_k<<<dim3(NC / 32, NHW / 32, NB), t32>>>(ao, x, out);
}

// round 5
// speedup vs baseline: 5.7485x; 1.1391x over previous
#include <cuda_runtime.h>
#include <math.h>
#include <stdint.h>

// ---------------- problem constants ----------------
#define NB    8
#define NC    512
#define NHW   1024
#define NTOK  8192
#define ND    512
#define NDC   768
#define NL    77
#define NLP   96
#define NHEAD 8
#define HDIM  64
#define NFF   2048
#define EPSV  1e-5f

// ---------------- scratch ----------------
__device__ float g_xn [(size_t)NTOK*ND];
__device__ float g_h  [(size_t)NTOK*ND];
__device__ float g_hn [(size_t)NTOK*ND];
__device__ float g_q  [(size_t)NTOK*ND];
__device__ float g_k  [(size_t)NTOK*ND];
__device__ float g_v  [(size_t)NTOK*ND];
__device__ float g_sim[(size_t)NB*NHEAD*NHW*NLP];   // cross-attn scores only now
__device__ float g_ao [(size_t)NTOK*ND];
__device__ float g_ff [(size_t)NTOK*NFF];
__device__ float g_gmean[NB*32];
__device__ float g_grstd[NB*32];

// ---------------- PTX helpers ----------------
__device__ __forceinline__ uint32_t smem_u32(const void* p) {
    uint32_t a;
    asm("{ .reg .u64 t; cvta.to.shared.u64 t, %1; cvt.u32.u64 %0, t; }" : "=r"(a) : "l"(p));
    return a;
}
__device__ __forceinline__ void cp16(uint32_t dst, const void* src, bool pred) {
    int sz = pred ? 16 : 0;
    asm volatile("cp.async.cg.shared.global [%0], [%1], 16, %2;\n" :: "r"(dst), "l"(src), "r"(sz));
}
#define MMA_TF32(acc, a0,a1,a2,a3, b0,b1) \
    asm volatile("mma.sync.aligned.m16n8k8.row.col.f32.tf32.tf32.f32 " \
        "{%0,%1,%2,%3}, {%4,%5,%6,%7}, {%8,%9}, {%0,%1,%2,%3};" \
        : "+f"((acc)[0]), "+f"((acc)[1]), "+f"((acc)[2]), "+f"((acc)[3]) \
        : "r"(a0), "r"(a1), "r"(a2), "r"(a3), "r"(b0), "r"(b1))

// ================= tf32 warp-MMA GEMM, cp.async 3-stage pipeline ==========
template<int BN, bool TRANSB>
__global__ __launch_bounds__(256)
void mma_gemm_k(const float* __restrict__ A, const float* __restrict__ Bm,
                float* __restrict__ C,
                int M, int N, int K, int lda, int ldb, int ldc, int bh,
                long long sA1, long long sA2, long long sB1, long long sB2,
                long long sC1, long long sC2,
                const float* __restrict__ bias,
                const float* __restrict__ res,
                int gelu) {
    constexpr int SA = 36;
    constexpr int SB = TRANSB ? 36 : (BN + 8);
    constexpr int AW = 128 * SA;
    constexpr int BW = TRANSB ? BN * 36 : 32 * (BN + 8);
    constexpr int STW = AW + BW;
    constexpr int WN = BN / 2;
    constexpr int NF = WN / 8;

    extern __shared__ float sm[];

    int z = blockIdx.z, zb = z / bh, zh = z - zb * bh;
    A  += (long long)zb * sA1 + (long long)zh * sA2;
    Bm += (long long)zb * sB1 + (long long)zh * sB2;
    long long coff = (long long)zb * sC1 + (long long)zh * sC2;
    C += coff;
    if (res) res += coff;

    int tid = threadIdx.x;
    int warp = tid >> 5, lane = tid & 31;
    int wm = warp & 3, wn = warp >> 2;
    int lr = lane >> 2, lc = lane & 3;
    int m0 = blockIdx.y * 128, n0 = blockIdx.x * BN;

    float acc[2][NF][4];
    #pragma unroll
    for (int i = 0; i < 2; i++)
        #pragma unroll
        for (int j = 0; j < NF; j++)
            #pragma unroll
            for (int l = 0; l < 4; l++) acc[i][j][l] = 0.f;

    int KT = K >> 5;

    auto load_tile = [&](int st, int kt) {
        float* As = sm + st * STW;
        float* Bs = As + AW;
        int k0 = kt << 5;
        #pragma unroll
        for (int i = 0; i < 4; i++) {
            int idx = tid + i * 256;
            int m = idx >> 3, c = idx & 7;
            int gm = m0 + m;
            int gs = gm < M ? gm : M - 1;
            cp16(smem_u32(&As[m * SA + c * 4]),
                 A + (long long)gs * lda + k0 + c * 4, gm < M);
        }
        if (TRANSB) {
            #pragma unroll
            for (int i = 0; i < BN / 32; i++) {
                int idx = tid + i * 256;
                int n = idx >> 3, c = idx & 7;
                int gn = n0 + n;
                int gs = gn < N ? gn : N - 1;
                cp16(smem_u32(&Bs[n * SB + c * 4]),
                     Bm + (long long)gs * ldb + k0 + c * 4, gn < N);
            }
        } else {
            constexpr int CPB = BN / 4;
            #pragma unroll
            for (int i = 0; i < BN / 32; i++) {
                int idx = tid + i * 256;
                int kk = idx / CPB, c = idx % CPB;
                cp16(smem_u32(&Bs[kk * SB + c * 4]),
                     Bm + (long long)(k0 + kk) * ldb + n0 + c * 4, true);
            }
        }
        asm volatile("cp.async.commit_group;\n" ::: "memory");
    };

    load_tile(0, 0);
    load_tile(1 % 3, 1 < KT ? 1 : 0);

    for (int kt = 0; kt < KT; kt++) {
        if (kt + 1 < KT) { asm volatile("cp.async.wait_group 1;\n" ::: "memory"); }
        else             { asm volatile("cp.async.wait_group 0;\n" ::: "memory"); }
        __syncthreads();
        if (kt + 2 < KT) load_tile((kt + 2) % 3, kt + 2);

        const float* As = sm + (kt % 3) * STW;
        const float* Bs = As + AW;
        #pragma unroll
        for (int ks4 = 0; ks4 < 4; ks4++) {
            int ks = ks4 * 8;
            uint32_t af[2][4];
            #pragma unroll
            for (int mt = 0; mt < 2; mt++) {
                int mr = wm * 32 + mt * 16;
                af[mt][0] = __float_as_uint(As[(mr + lr    ) * SA + ks + lc    ]);
                af[mt][1] = __float_as_uint(As[(mr + lr + 8) * SA + ks + lc    ]);
                af[mt][2] = __float_as_uint(As[(mr + lr    ) * SA + ks + lc + 4]);
                af[mt][3] = __float_as_uint(As[(mr + lr + 8) * SA + ks + lc + 4]);
            }
            uint32_t bf[NF][2];
            #pragma unroll
            for (int nt = 0; nt < NF; nt++) {
                int nc = wn * WN + nt * 8 + lr;
                if (TRANSB) {
                    bf[nt][0] = __float_as_uint(Bs[nc * SB + ks + lc    ]);
                    bf[nt][1] = __float_as_uint(Bs[nc * SB + ks + lc + 4]);
                } else {
                    bf[nt][0] = __float_as_uint(Bs[(ks + lc    ) * SB + nc]);
                    bf[nt][1] = __float_as_uint(Bs[(ks + lc + 4) * SB + nc]);
                }
            }
            #pragma unroll
            for (int mt = 0; mt < 2; mt++)
                #pragma unroll
                for (int nt = 0; nt < NF; nt++)
                    MMA_TF32(acc[mt][nt], af[mt][0], af[mt][1], af[mt][2], af[mt][3],
                             bf[nt][0], bf[nt][1]);
        }
    }

    #pragma unroll
    for (int mt = 0; mt < 2; mt++) {
        #pragma unroll
        for (int nt = 0; nt < NF; nt++) {
            int row0 = m0 + wm * 32 + mt * 16 + lr;
            int col0 = n0 + wn * WN + nt * 8 + 2 * lc;
            #pragma unroll
            for (int half = 0; half < 2; half++) {
                int gm = row0 + half * 8;
                if (gm >= M) continue;
                #pragma unroll
                for (int j = 0; j < 2; j++) {
                    int gn = col0 + j;
                    if (gn >= N) continue;
                    float r = acc[mt][nt][half * 2 + j];
                    if (bias) r += bias[gn];
                    if (res)  r += res[(long long)gm * ldc + gn];
                    if (gelu) r = 0.5f * r * (1.f + erff(r * 0.70710678118654752f));
                    C[(long long)gm * ldc + gn] = r;
                }
            }
        }
    }
}

// ================= fused flash self-attention =============================
// Per CTA: 128 Q rows of one (b,h). K/V tiles of 64 tokens, double-buffered.
// smem: Ks[2][64*68], Vs[2][64*72], Ps[128*68]
#define KS_ST 68
#define VS_ST 72
#define PS_ST 68
#define KS_STG (64*KS_ST)
#define VS_STG (64*VS_ST)
#define FA_SMEM ((2*KS_STG + 2*VS_STG + 128*PS_ST) * 4)

__global__ __launch_bounds__(256, 1)
void flash_attn_k(const float* __restrict__ Q, const float* __restrict__ K,
                  const float* __restrict__ V, float* __restrict__ O) {
    extern __shared__ float sm[];
    float* Ks = sm;
    float* Vs = sm + 2 * KS_STG;
    float* Ps = sm + 2 * KS_STG + 2 * VS_STG;

    int tid = threadIdx.x, warp = tid >> 5, lane = tid & 31;
    int lr = lane >> 2, lc = lane & 3;
    int bq = blockIdx.x;             // q block 0..7
    int bh = blockIdx.y;             // 0..63
    int b = bh >> 3, hh = bh & 7;

    const float* Qb = Q + (size_t)(b * NHW) * ND + hh * HDIM;
    const float* Kb = K + (size_t)(b * NHW) * ND + hh * HDIM;
    const float* Vb = V + (size_t)(b * NHW) * ND + hh * HDIM;
    int qrow0 = bq * 128 + warp * 16;

    // Q A-fragments, pre-scaled by 1/sqrt(64)
    float qf[8][4];
    #pragma unroll
    for (int kf = 0; kf < 8; kf++) {
        qf[kf][0] = Qb[(size_t)(qrow0 + lr    ) * ND + kf * 8 + lc    ] * 0.125f;
        qf[kf][1] = Qb[(size_t)(qrow0 + lr + 8) * ND + kf * 8 + lc    ] * 0.125f;
        qf[kf][2] = Qb[(size_t)(qrow0 + lr    ) * ND + kf * 8 + lc + 4] * 0.125f;
        qf[kf][3] = Qb[(size_t)(qrow0 + lr + 8) * ND + kf * 8 + lc + 4] * 0.125f;
    }

    float oacc[8][4];
    #pragma unroll
    for (int i = 0; i < 8; i++)
        #pragma unroll
        for (int j = 0; j < 4; j++) oacc[i][j] = 0.f;
    float m0r = -1e30f, m1r = -1e30f, l0r = 0.f, l1r = 0.f;

    auto load_kv = [&](int st, int j) {
        int t0 = j * 64;
        #pragma unroll
        for (int i = 0; i < 4; i++) {
            int idx = tid + i * 256;
            int r = idx >> 4, c = idx & 15;
            cp16(smem_u32(&Ks[st * KS_STG + r * KS_ST + c * 4]),
                 Kb + (size_t)(t0 + r) * ND + c * 4, true);
        }
        #pragma unroll
        for (int i = 0; i < 4; i++) {
            int idx = tid + i * 256;
            int r = idx >> 4, c = idx & 15;
            cp16(smem_u32(&Vs[st * VS_STG + r * VS_ST + c * 4]),
                 Vb + (size_t)(t0 + r) * ND + c * 4, true);
        }
        asm volatile("cp.async.commit_group;\n" ::: "memory");
    };

    load_kv(0, 0);
    for (int j = 0; j < 16; j++) {
        int st = j & 1;
        __syncthreads();                     // stage st^1 & Ps free for reuse
        if (j + 1 < 16) {
            load_kv(st ^ 1, j + 1);
            asm volatile("cp.async.wait_group 1;\n" ::: "memory");
        } else {
            asm volatile("cp.async.wait_group 0;\n" ::: "memory");
        }
        __syncthreads();
        const float* Kt = Ks + st * KS_STG;
        const float* Vt = Vs + st * VS_STG;

        // ---- S = Qw @ Kt^T  (16 x 64 per warp)
        float sacc[8][4];
        #pragma unroll
        for (int i = 0; i < 8; i++)
            #pragma unroll
            for (int l = 0; l < 4; l++) sacc[i][l] = 0.f;
        #pragma unroll
        for (int ks = 0; ks < 8; ks++) {
            uint32_t a0 = __float_as_uint(qf[ks][0]);
            uint32_t a1 = __float_as_uint(qf[ks][1]);
            uint32_t a2 = __float_as_uint(qf[ks][2]);
            uint32_t a3 = __float_as_uint(qf[ks][3]);
            #pragma unroll
            for (int nt = 0; nt < 8; nt++) {
                uint32_t b0 = __float_as_uint(Kt[(nt * 8 + lr) * KS_ST + ks * 8 + lc    ]);
                uint32_t b1 = __float_as_uint(Kt[(nt * 8 + lr) * KS_ST + ks * 8 + lc + 4]);
                MMA_TF32(sacc[nt], a0, a1, a2, a3, b0, b1);
            }
        }

        // ---- online softmax (rows lr and lr+8; stats replicated over lc quad)
        float mx0 = -1e30f, mx1 = -1e30f;
        #pragma unroll
        for (int nt = 0; nt < 8; nt++) {
            mx0 = fmaxf(mx0, fmaxf(sacc[nt][0], sacc[nt][1]));
            mx1 = fmaxf(mx1, fmaxf(sacc[nt][2], sacc[nt][3]));
        }
        mx0 = fmaxf(mx0, __shfl_xor_sync(0xffffffffu, mx0, 1));
        mx0 = fmaxf(mx0, __shfl_xor_sync(0xffffffffu, mx0, 2));
        mx1 = fmaxf(mx1, __shfl_xor_sync(0xffffffffu, mx1, 1));
        mx1 = fmaxf(mx1, __shfl_xor_sync(0xffffffffu, mx1, 2));
        float mn0 = fmaxf(m0r, mx0), mn1 = fmaxf(m1r, mx1);
        float f0 = __expf(m0r - mn0), f1 = __expf(m1r - mn1);
        float s0 = 0.f, s1 = 0.f;
        int prow = warp * 16 + lr;
        #pragma unroll
        for (int nt = 0; nt < 8; nt++) {
            float p00 = __expf(sacc[nt][0] - mn0);
            float p01 = __expf(sacc[nt][1] - mn0);
            float p10 = __expf(sacc[nt][2] - mn1);
            float p11 = __expf(sacc[nt][3] - mn1);
            s0 += p00 + p01; s1 += p10 + p11;
            Ps[(prow    ) * PS_ST + nt * 8 + 2 * lc    ] = p00;
            Ps[(prow    ) * PS_ST + nt * 8 + 2 * lc + 1] = p01;
            Ps[(prow + 8) * PS_ST + nt * 8 + 2 * lc    ] = p10;
            Ps[(prow + 8) * PS_ST + nt * 8 + 2 * lc + 1] = p11;
            oacc[nt][0] *= f0; oacc[nt][1] *= f0;
            oacc[nt][2] *= f1; oacc[nt][3] *= f1;
        }
        s0 += __shfl_xor_sync(0xffffffffu, s0, 1);
        s0 += __shfl_xor_sync(0xffffffffu, s0, 2);
        s1 += __shfl_xor_sync(0xffffffffu, s1, 1);
        s1 += __shfl_xor_sync(0xffffffffu, s1, 2);
        l0r = l0r * f0 + s0; l1r = l1r * f1 + s1;
        m0r = mn0; m1r = mn1;
        __syncthreads();                     // P visible to own warp reads (layout-safe) & all

        // ---- O += P @ Vt   (k = 64 tile tokens)
        #pragma unroll
        for (int ks = 0; ks < 8; ks++) {
            uint32_t a0 = __float_as_uint(Ps[(prow    ) * PS_ST + ks * 8 + lc    ]);
            uint32_t a1 = __float_as_uint(Ps[(prow + 8) * PS_ST + ks * 8 + lc    ]);
            uint32_t a2 = __float_as_uint(Ps[(prow    ) * PS_ST + ks * 8 + lc + 4]);
            uint32_t a3 = __float_as_uint(Ps[(prow + 8) * PS_ST + ks * 8 + lc + 4]);
            #pragma unroll
            for (int nt = 0; nt < 8; nt++) {
                uint32_t b0 = __float_as_uint(Vt[(ks * 8 + lc    ) * VS_ST + nt * 8 + lr]);
                uint32_t b1 = __float_as_uint(Vt[(ks * 8 + lc + 4) * VS_ST + nt * 8 + lr]);
                MMA_TF32(oacc[nt], a0, a1, a2, a3, b0, b1);
            }
        }
    }

    // ---- normalize + store
    float inv0 = 1.f / l0r, inv1 = 1.f / l1r;
    float* Ob = O + (size_t)(b * NHW) * ND + hh * HDIM;
    #pragma unroll
    for (int nt = 0; nt < 8; nt++) {
        int col = nt * 8 + 2 * lc;
        Ob[(size_t)(qrow0 + lr    ) * ND + col    ] = oacc[nt][0] * inv0;
        Ob[(size_t)(qrow0 + lr    ) * ND + col + 1] = oacc[nt][1] * inv0;
        Ob[(size_t)(qrow0 + lr + 8) * ND + col    ] = oacc[nt][2] * inv1;
        Ob[(size_t)(qrow0 + lr + 8) * ND + col + 1] = oacc[nt][3] * inv1;
    }
}

// ================= small kernels =================
__device__ __forceinline__ float blk_reduce(float v, int is_max) {
    __shared__ float sh[33];
    int lane = threadIdx.x & 31, w = threadIdx.x >> 5;
    #pragma unroll
    for (int o = 16; o; o >>= 1) {
        float t = __shfl_down_sync(0xffffffffu, v, o);
        v = is_max ? fmaxf(v, t) : v + t;
    }
    if (!lane) sh[w] = v;
    __syncthreads();
    int nw = blockDim.x >> 5;
    v = (threadIdx.x < nw) ? sh[threadIdx.x] : (is_max ? -1e30f : 0.0f);
    if (w == 0) {
        #pragma unroll
        for (int o = 16; o; o >>= 1) {
            float t = __shfl_down_sync(0xffffffffu, v, o);
            v = is_max ? fmaxf(v, t) : v + t;
        }
        if (threadIdx.x == 0) sh[32] = v;
    }
    __syncthreads();
    float r = sh[32];
    __syncthreads();
    return r;
}

__global__ void gn_stats_k(const float* __restrict__ x, float* __restrict__ mean,
                           float* __restrict__ rstd) {
    int bg = blockIdx.x;
    const float* p = x + (size_t)bg * 16384;
    float s = 0.f, s2 = 0.f;
    for (int i = threadIdx.x; i < 16384; i += 256) {
        float v = p[i];
        s += v; s2 += v * v;
    }
    s  = blk_reduce(s, 0);
    s2 = blk_reduce(s2, 0);
    if (threadIdx.x == 0) {
        float mu  = s * (1.f / 16384.f);
        float var = s2 * (1.f / 16384.f) - mu * mu;
        mean[bg] = mu;
        rstd[bg] = rsqrtf(var + EPSV);
    }
}

__global__ void gn_apply_k(const float* __restrict__ x, const float* __restrict__ gamma,
                           const float* __restrict__ beta, const float* __restrict__ mean,
                           const float* __restrict__ rstd, float* __restrict__ xn) {
    __shared__ float tile[32][33];
    int b = blockIdx.z;
    int c0 = blockIdx.y * 32, hw0 = blockIdx.x * 32;
    int c = c0 + threadIdx.y, hw = hw0 + threadIdx.x;
    float v = x[((size_t)b * NC + c) * NHW + hw];
    int grp = c >> 4;
    float mu = mean[b * 32 + grp], rs = rstd[b * 32 + grp];
    tile[threadIdx.y][threadIdx.x] = (v - mu) * rs * gamma[c] + beta[c];
    __syncthreads();
    xn[((size_t)b * NHW + hw0 + threadIdx.y) * ND + c0 + threadIdx.x] =
        tile[threadIdx.x][threadIdx.y];
}

__global__ void ln_k(const float* __restrict__ x, const float* __restrict__ g,
                     const float* __restrict__ b, float* __restrict__ y) {
    size_t row = blockIdx.x;
    const float* xr = x + row * ND;
    float* yr = y + row * ND;
    int t = threadIdx.x;
    float v0 = xr[t], v1 = xr[t + 256];
    float s  = blk_reduce(v0 + v1, 0);
    float s2 = blk_reduce(v0 * v0 + v1 * v1, 0);
    float mu = s * (1.f / ND);
    float rs = rsqrtf(s2 * (1.f / ND) - mu * mu + EPSV);
    yr[t]       = (v0 - mu) * rs * g[t]       + b[t];
    yr[t + 256] = (v1 - mu) * rs * g[t + 256] + b[t + 256];
}

// cross softmax: rows of stride 96, valid cols 77, zero the pad
__global__ void softmax_cross_k(float* __restrict__ s, float scale) {
    int row = blockIdx.x * 8 + (threadIdx.x >> 5);
    int lane = threadIdx.x & 31;
    float* p = s + (size_t)row * NLP;
    float a0 = p[lane] * scale;
    float a1 = (lane + 32 < NL) ? p[lane + 32] * scale : -1e30f;
    float a2 = (lane + 64 < NL) ? p[lane + 64] * scale : -1e30f;
    float m = fmaxf(a0, fmaxf(a1, a2));
    #pragma unroll
    for (int o = 16; o; o >>= 1) m = fmaxf(m, __shfl_xor_sync(0xffffffffu, m, o));
    float e0 = __expf(a0 - m);
    float e1 = (lane + 32 < NL) ? __expf(a1 - m) : 0.f;
    float e2 = (lane + 64 < NL) ? __expf(a2 - m) : 0.f;
    float t = e0 + e1 + e2;
    #pragma unroll
    for (int o = 16; o; o >>= 1) t += __shfl_xor_sync(0xffffffffu, t, o);
    float inv = 1.f / t;
    p[lane] = e0 * inv;
    p[lane + 32] = (lane + 32 < NL) ? e1 * inv : 0.f;
    p[lane + 64] = (lane + 64 < NL) ? e2 * inv : 0.f;
}

__global__ void out_add_k(const float* __restrict__ t, const float* __restrict__ x_in,
                          float* __restrict__ out) {
    __shared__ float tile[32][33];
    int b = blockIdx.z;
    int c0 = blockIdx.x * 32, hw0 = blockIdx.y * 32;
    tile[threadIdx.y][threadIdx.x] =
        t[((size_t)b * NHW + hw0 + threadIdx.y) * ND + c0 + threadIdx.x];
    __syncthreads();
    size_t o = ((size_t)b * NC + c0 + threadIdx.y) * NHW + hw0 + threadIdx.x;
    out[o] = tile[threadIdx.x][threadIdx.y] + x_in[o];
}

// ================= host =================
template<int BN, bool TRANSB>
static void tcl(const float* A, const float* B, float* C,
                int M, int N, int K, int lda, int ldb, int ldc,
                const float* bias, const float* res, int gelu,
                int batch = 1, int bh = 1,
                long long sA1 = 0, long long sA2 = 0,
                long long sB1 = 0, long long sB2 = 0,
                long long sC1 = 0, long long sC2 = 0) {
    constexpr int AW = 128 * 36;
    constexpr int BW = TRANSB ? BN * 36 : 32 * (BN + 8);
    int smem = 3 * (AW + BW) * 4;
    static bool attr_set = false;
    if (!attr_set) {
        cudaFuncSetAttribute(mma_gemm_k<BN, TRANSB>,
                             cudaFuncAttributeMaxDynamicSharedMemorySize, smem);
        attr_set = true;
    }
    dim3 grid((N + BN - 1) / BN, (M + 127) / 128, batch);
    mma_gemm_k<BN, TRANSB><<<grid, 256, smem>>>(A, B, C, M, N, K, lda, ldb, ldc, bh,
                                                sA1, sA2, sB1, sB2, sC1, sC2,
                                                bias, res, gelu);
}

extern "C" void kernel_launch(void* const* d_in, const int* in_sizes, int n_in,
                              void* d_out, int out_size) {
    const float* x      = (const float*)d_in[0];
    const float* ctx    = (const float*)d_in[1];
    const float* gn_g   = (const float*)d_in[2];
    const float* gn_b   = (const float*)d_in[3];
    const float* pin_w  = (const float*)d_in[4];
    const float* pin_b  = (const float*)d_in[5];
    const float* ln1_g  = (const float*)d_in[6];
    const float* ln1_b  = (const float*)d_in[7];
    const float* q1_w   = (const float*)d_in[8];
    const float* k1_w   = (const float*)d_in[9];
    const float* v1_w   = (const float*)d_in[10];
    const float* o1_w   = (const float*)d_in[11];
    const float* o1_b   = (const float*)d_in[12];
    const float* ln2_g  = (const float*)d_in[13];
    const float* ln2_b  = (const float*)d_in[14];
    const float* q2_w   = (const float*)d_in[15];
    const float* k2_w   = (const float*)d_in[16];
    const float* v2_w   = (const float*)d_in[17];
    const float* o2_w   = (const float*)d_in[18];
    const float* o2_b   = (const float*)d_in[19];
    const float* ln3_g  = (const float*)d_in[20];
    const float* ln3_b  = (const float*)d_in[21];
    const float* ff1_w  = (const float*)d_in[22];
    const float* ff1_b  = (const float*)d_in[23];
    const float* ff2_w  = (const float*)d_in[24];
    const float* ff2_b  = (const float*)d_in[25];
    const float* pout_w = (const float*)d_in[26];
    const float* pout_b = (const float*)d_in[27];
    float* out = (float*)d_out;

    float *xn, *h, *hn, *q, *k, *v, *sim, *ao, *ff, *gmean, *grstd;
    cudaGetSymbolAddress((void**)&xn,    g_xn);
    cudaGetSymbolAddress((void**)&h,     g_h);
    cudaGetSymbolAddress((void**)&hn,    g_hn);
    cudaGetSymbolAddress((void**)&q,     g_q);
    cudaGetSymbolAddress((void**)&k,     g_k);
    cudaGetSymbolAddress((void**)&v,     g_v);
    cudaGetSymbolAddress((void**)&sim,   g_sim);
    cudaGetSymbolAddress((void**)&ao,    g_ao);
    cudaGetSymbolAddress((void**)&ff,    g_ff);
    cudaGetSymbolAddress((void**)&gmean, g_gmean);
    cudaGetSymbolAddress((void**)&grstd, g_grstd);

    const float scale = 0.125f;
    dim3 t32(32, 32);

    static bool fa_attr = false;
    if (!fa_attr) {
        cudaFuncSetAttribute(flash_attn_k,
                             cudaFuncAttributeMaxDynamicSharedMemorySize, FA_SMEM);
        fa_attr = true;
    }

    // 1) GroupNorm + transpose to token-major
    gn_stats_k<<<NB * 32, 256>>>(x, gmean, grstd);
    gn_apply_k<<<dim3(NHW / 32, NC / 32, NB), t32>>>(x, gn_g, gn_b, gmean, grstd, xn);

    // 2) proj_in
    tcl<128, false>(xn, pin_w, h, NTOK, ND, ND, ND, ND, ND, pin_b, nullptr, 0);

    // 3) self-attention (fused flash)
    ln_k<<<NTOK, 256>>>(h, ln1_g, ln1_b, hn);
    tcl<128, false>(hn, q1_w, q, NTOK, ND, ND, ND, ND, ND, nullptr, nullptr, 0);
    tcl<128, false>(hn, k1_w, k, NTOK, ND, ND, ND, ND, ND, nullptr, nullptr, 0);
    tcl<128, false>(hn, v1_w, v, NTOK, ND, ND, ND, ND, ND, nullptr, nullptr, 0);
    flash_attn_k<<<dim3(NHW / 128, NB * NHEAD), 256, FA_SMEM>>>(q, k, v, ao);
    tcl<128, false>(ao, o1_w, h, NTOK, ND, ND, ND, ND, ND, o1_b, h, 0);

    // 4) cross-attention
    ln_k<<<NTOK, 256>>>(h, ln2_g, ln2_b, hn);
    tcl<128, false>(hn, q2_w, q, NTOK, ND, ND, ND, ND, ND, nullptr, nullptr, 0);
    tcl<128, false>(ctx, k2_w, k, NB * NL, ND, NDC, NDC, ND, ND, nullptr, nullptr, 0);
    tcl<128, false>(ctx, v2_w, v, NB * NL, ND, NDC, NDC, ND, ND, nullptr, nullptr, 0);
    tcl<128, true>(q, k, sim, NHW, NLP, HDIM, ND, ND, NLP, nullptr, nullptr, 0,
                   NB * NHEAD, NHEAD,
                   (long long)NHW * ND, HDIM,
                   (long long)NL * ND, HDIM,
                   (long long)NHEAD * NHW * NLP, (long long)NHW * NLP);
    softmax_cross_k<<<NB * NHEAD * NHW / 8, 256>>>(sim, scale);
    tcl<64, false>(sim, v, ao, NHW, HDIM, NLP, NLP, ND, ND, nullptr, nullptr, 0,
                   NB * NHEAD, NHEAD,
                   (long long)NHEAD * NHW * NLP, (long long)NHW * NLP,
                   (long long)NL * ND, HDIM,
                   (long long)NHW * ND, HDIM);
    tcl<128, false>(ao, o2_w, h, NTOK, ND, ND, ND, ND, ND, o2_b, h, 0);

    // 5) feed-forward
    ln_k<<<NTOK, 256>>>(h, ln3_g, ln3_b, hn);
    tcl<128, false>(hn, ff1_w, ff, NTOK, NFF, ND, ND, NFF, NFF, ff1_b, nullptr, 1);
    tcl<128, false>(ff, ff2_w, h, NTOK, ND, NFF, NFF, ND, ND, ff2_b, h, 0);

    // 6) proj_out + input residual
    tcl<128, false>(h, pout_w, ao, NTOK, NC, ND, ND, NC, NC, pout_b, nullptr, 0);
    out_add_k<<<dim3(NC / 32, NHW / 32, NB), t32>>>(ao, x, out);
}

// round 7
// speedup vs baseline: 5.8183x; 1.0122x over previous
#include <cuda_runtime.h>
#include <math.h>
#include <stdint.h>

// ---------------- problem constants ----------------
#define NB    8
#define NC    512
#define NHW   1024
#define NTOK  8192
#define ND    512
#define NDC   768
#define NL    77
#define NHEAD 8
#define HDIM  64
#define NFF   2048
#define EPSV  1e-5f

// ---------------- scratch ----------------
__device__ float g_xn [(size_t)NTOK*ND];
__device__ float g_h  [(size_t)NTOK*ND];
__device__ float g_hn [(size_t)NTOK*ND];
__device__ float g_q  [(size_t)NTOK*ND];
__device__ float g_k  [(size_t)NTOK*ND];
__device__ float g_v  [(size_t)NTOK*ND];
__device__ float g_ao [(size_t)NTOK*ND];
__device__ float g_ff [(size_t)NTOK*NFF];
__device__ float g_gmean[NB*32];
__device__ float g_grstd[NB*32];

// ---------------- PTX helpers ----------------
__device__ __forceinline__ uint32_t smem_u32(const void* p) {
    uint32_t a;
    asm("{ .reg .u64 t; cvta.to.shared.u64 t, %1; cvt.u32.u64 %0, t; }" : "=r"(a) : "l"(p));
    return a;
}
__device__ __forceinline__ void cp16(uint32_t dst, const void* src, bool pred) {
    int sz = pred ? 16 : 0;   // sz=0 -> 16B zero-fill
    asm volatile("cp.async.cg.shared.global [%0], [%1], 16, %2;\n" :: "r"(dst), "l"(src), "r"(sz));
}
#define MMA_TF32(acc, a0,a1,a2,a3, b0,b1) \
    asm volatile("mma.sync.aligned.m16n8k8.row.col.f32.tf32.tf32.f32 " \
        "{%0,%1,%2,%3}, {%4,%5,%6,%7}, {%8,%9}, {%0,%1,%2,%3};" \
        : "+f"((acc)[0]), "+f"((acc)[1]), "+f"((acc)[2]), "+f"((acc)[3]) \
        : "r"(a0), "r"(a1), "r"(a2), "r"(a3), "r"(b0), "r"(b1))

// ================= tf32 warp-MMA GEMM, cp.async 3-stage + frag pipeline ===
template<int BN, bool TRANSB>
__global__ __launch_bounds__(256)
void mma_gemm_k(const float* __restrict__ A, const float* __restrict__ Bm,
                float* __restrict__ C,
                int M, int N, int K, int lda, int ldb, int ldc, int bh,
                long long sA1, long long sA2, long long sB1, long long sB2,
                long long sC1, long long sC2,
                const float* __restrict__ bias,
                const float* __restrict__ res,
                int gelu) {
    constexpr int SA = 36;
    constexpr int SB = TRANSB ? 36 : (BN + 8);
    constexpr int AW = 128 * SA;
    constexpr int BW = TRANSB ? BN * 36 : 32 * (BN + 8);
    constexpr int STW = AW + BW;
    constexpr int WN = BN / 2;
    constexpr int NF = WN / 8;

    extern __shared__ float sm[];

    int z = blockIdx.z, zb = z / bh, zh = z - zb * bh;
    A  += (long long)zb * sA1 + (long long)zh * sA2;
    Bm += (long long)zb * sB1 + (long long)zh * sB2;
    long long coff = (long long)zb * sC1 + (long long)zh * sC2;
    C += coff;
    if (res) res += coff;

    int tid = threadIdx.x;
    int warp = tid >> 5, lane = tid & 31;
    int wm = warp & 3, wn = warp >> 2;
    int lr = lane >> 2, lc = lane & 3;
    int m0 = blockIdx.y * 128, n0 = blockIdx.x * BN;

    float acc[2][NF][4];
    #pragma unroll
    for (int i = 0; i < 2; i++)
        #pragma unroll
        for (int j = 0; j < NF; j++)
            #pragma unroll
            for (int l = 0; l < 4; l++) acc[i][j][l] = 0.f;

    int KT = K >> 5;

    auto load_tile = [&](int st, int kt) {
        float* As = sm + st * STW;
        float* Bs = As + AW;
        int k0 = kt << 5;
        #pragma unroll
        for (int i = 0; i < 4; i++) {
            int idx = tid + i * 256;
            int m = idx >> 3, c = idx & 7;
            int gm = m0 + m;
            int gs = gm < M ? gm : M - 1;
            cp16(smem_u32(&As[m * SA + c * 4]),
                 A + (long long)gs * lda + k0 + c * 4, gm < M);
        }
        if (TRANSB) {
            #pragma unroll
            for (int i = 0; i < BN / 32; i++) {
                int idx = tid + i * 256;
                int n = idx >> 3, c = idx & 7;
                int gn = n0 + n;
                int gs = gn < N ? gn : N - 1;
                cp16(smem_u32(&Bs[n * SB + c * 4]),
                     Bm + (long long)gs * ldb + k0 + c * 4, gn < N);
            }
        } else {
            constexpr int CPB = BN / 4;
            #pragma unroll
            for (int i = 0; i < BN / 32; i++) {
                int idx = tid + i * 256;
                int kk = idx / CPB, c = idx % CPB;
                cp16(smem_u32(&Bs[kk * SB + c * 4]),
                     Bm + (long long)(k0 + kk) * ldb + n0 + c * 4, true);
            }
        }
        asm volatile("cp.async.commit_group;\n" ::: "memory");
    };

    load_tile(0, 0);
    load_tile(1 % 3, 1 < KT ? 1 : 0);

    uint32_t af[2][2][4];
    uint32_t bf[2][NF][2];

    for (int kt = 0; kt < KT; kt++) {
        if (kt + 1 < KT) { asm volatile("cp.async.wait_group 1;\n" ::: "memory"); }
        else             { asm volatile("cp.async.wait_group 0;\n" ::: "memory"); }
        __syncthreads();
        if (kt + 2 < KT) load_tile((kt + 2) % 3, kt + 2);

        const float* As = sm + (kt % 3) * STW;
        const float* Bs = As + AW;

        // fragment loader for one k-step of 8
        auto load_frags = [&](int ks4, int buf) {
            int ks = ks4 * 8;
            #pragma unroll
            for (int mt = 0; mt < 2; mt++) {
                int mr = wm * 32 + mt * 16;
                af[buf][mt][0] = __float_as_uint(As[(mr + lr    ) * SA + ks + lc    ]);
                af[buf][mt][1] = __float_as_uint(As[(mr + lr + 8) * SA + ks + lc    ]);
                af[buf][mt][2] = __float_as_uint(As[(mr + lr    ) * SA + ks + lc + 4]);
                af[buf][mt][3] = __float_as_uint(As[(mr + lr + 8) * SA + ks + lc + 4]);
            }
            #pragma unroll
            for (int nt = 0; nt < NF; nt++) {
                int nc = wn * WN + nt * 8 + lr;
                if (TRANSB) {
                    bf[buf][nt][0] = __float_as_uint(Bs[nc * SB + ks + lc    ]);
                    bf[buf][nt][1] = __float_as_uint(Bs[nc * SB + ks + lc + 4]);
                } else {
                    bf[buf][nt][0] = __float_as_uint(Bs[(ks + lc    ) * SB + nc]);
                    bf[buf][nt][1] = __float_as_uint(Bs[(ks + lc + 4) * SB + nc]);
                }
            }
        };

        load_frags(0, 0);
        #pragma unroll
        for (int ks4 = 0; ks4 < 4; ks4++) {
            int cur = ks4 & 1;
            if (ks4 < 3) load_frags(ks4 + 1, cur ^ 1);
            #pragma unroll
            for (int mt = 0; mt < 2; mt++)
                #pragma unroll
                for (int nt = 0; nt < NF; nt++)
                    MMA_TF32(acc[mt][nt],
                             af[cur][mt][0], af[cur][mt][1], af[cur][mt][2], af[cur][mt][3],
                             bf[cur][nt][0], bf[cur][nt][1]);
        }
    }

    #pragma unroll
    for (int mt = 0; mt < 2; mt++) {
        #pragma unroll
        for (int nt = 0; nt < NF; nt++) {
            int row0 = m0 + wm * 32 + mt * 16 + lr;
            int col0 = n0 + wn * WN + nt * 8 + 2 * lc;
            #pragma unroll
            for (int half = 0; half < 2; half++) {
                int gm = row0 + half * 8;
                if (gm >= M) continue;
                #pragma unroll
                for (int j = 0; j < 2; j++) {
                    int gn = col0 + j;
                    if (gn >= N) continue;
                    float r = acc[mt][nt][half * 2 + j];
                    if (bias) r += bias[gn];
                    if (res)  r += res[(long long)gm * ldc + gn];
                    if (gelu) r = 0.5f * r * (1.f + erff(r * 0.70710678118654752f));
                    C[(long long)gm * ldc + gn] = r;
                }
            }
        }
    }
}

// ================= fused flash attention (self & cross) ===================
// NT KV tiles of 64 tokens; KVLEN valid tokens; KVTOK = per-batch KV rows.
#define KS_ST 68
#define VS_ST 72
#define PS_ST 68
#define KS_STG (64*KS_ST)
#define VS_STG (64*VS_ST)
#define FA_SMEM ((2*KS_STG + 2*VS_STG + 128*PS_ST) * 4)

template<int NT, int KVLEN, int KVTOK>
__global__ __launch_bounds__(256, 1)
void flash_attn_k(const float* __restrict__ Q, const float* __restrict__ K,
                  const float* __restrict__ V, float* __restrict__ O) {
    constexpr bool MASK = (KVLEN & 63) != 0;
    extern __shared__ float sm[];
    float* Ks = sm;
    float* Vs = sm + 2 * KS_STG;
    float* Ps = sm + 2 * KS_STG + 2 * VS_STG;

    int tid = threadIdx.x, warp = tid >> 5, lane = tid & 31;
    int lr = lane >> 2, lc = lane & 3;
    int bq = blockIdx.x;
    int bh = blockIdx.y;
    int b = bh >> 3, hh = bh & 7;

    const float* Qb = Q + (size_t)(b * NHW) * ND + hh * HDIM;
    const float* Kb = K + (size_t)(b * KVTOK) * ND + hh * HDIM;
    const float* Vb = V + (size_t)(b * KVTOK) * ND + hh * HDIM;
    int qrow0 = bq * 128 + warp * 16;

    float qf[8][4];
    #pragma unroll
    for (int kf = 0; kf < 8; kf++) {
        qf[kf][0] = Qb[(size_t)(qrow0 + lr    ) * ND + kf * 8 + lc    ] * 0.125f;
        qf[kf][1] = Qb[(size_t)(qrow0 + lr + 8) * ND + kf * 8 + lc    ] * 0.125f;
        qf[kf][2] = Qb[(size_t)(qrow0 + lr    ) * ND + kf * 8 + lc + 4] * 0.125f;
        qf[kf][3] = Qb[(size_t)(qrow0 + lr + 8) * ND + kf * 8 + lc + 4] * 0.125f;
    }

    float oacc[8][4];
    #pragma unroll
    for (int i = 0; i < 8; i++)
        #pragma unroll
        for (int j = 0; j < 4; j++) oacc[i][j] = 0.f;
    float m0r = -1e30f, m1r = -1e30f, l0r = 0.f, l1r = 0.f;

    auto load_kv = [&](int st, int j) {
        int t0 = j * 64;
        #pragma unroll
        for (int i = 0; i < 4; i++) {
            int idx = tid + i * 256;
            int r = idx >> 4, c = idx & 15;
            bool ok = (t0 + r) < KVLEN;
            cp16(smem_u32(&Ks[st * KS_STG + r * KS_ST + c * 4]),
                 Kb + (size_t)(t0 + r) * ND + c * 4, ok);
        }
        #pragma unroll
        for (int i = 0; i < 4; i++) {
            int idx = tid + i * 256;
            int r = idx >> 4, c = idx & 15;
            bool ok = (t0 + r) < KVLEN;
            cp16(smem_u32(&Vs[st * VS_STG + r * VS_ST + c * 4]),
                 Vb + (size_t)(t0 + r) * ND + c * 4, ok);
        }
        asm volatile("cp.async.commit_group;\n" ::: "memory");
    };

    load_kv(0, 0);
    #pragma unroll 1
    for (int j = 0; j < NT; j++) {
        int st = j & 1;
        __syncthreads();
        if (j + 1 < NT) {
            load_kv(st ^ 1, j + 1);
            asm volatile("cp.async.wait_group 1;\n" ::: "memory");
        } else {
            asm volatile("cp.async.wait_group 0;\n" ::: "memory");
        }
        __syncthreads();
        const float* Kt = Ks + st * KS_STG;
        const float* Vt = Vs + st * VS_STG;

        float sacc[8][4];
        #pragma unroll
        for (int i = 0; i < 8; i++)
            #pragma unroll
            for (int l = 0; l < 4; l++) sacc[i][l] = 0.f;
        #pragma unroll
        for (int ks = 0; ks < 8; ks++) {
            uint32_t a0 = __float_as_uint(qf[ks][0]);
            uint32_t a1 = __float_as_uint(qf[ks][1]);
            uint32_t a2 = __float_as_uint(qf[ks][2]);
            uint32_t a3 = __float_as_uint(qf[ks][3]);
            #pragma unroll
            for (int nt = 0; nt < 8; nt++) {
                uint32_t b0 = __float_as_uint(Kt[(nt * 8 + lr) * KS_ST + ks * 8 + lc    ]);
                uint32_t b1 = __float_as_uint(Kt[(nt * 8 + lr) * KS_ST + ks * 8 + lc + 4]);
                MMA_TF32(sacc[nt], a0, a1, a2, a3, b0, b1);
            }
        }

        if (MASK && j == NT - 1) {
            #pragma unroll
            for (int nt = 0; nt < 8; nt++) {
                int c0 = j * 64 + nt * 8 + 2 * lc;
                if (c0     >= KVLEN) { sacc[nt][0] = -1e30f; sacc[nt][2] = -1e30f; }
                if (c0 + 1 >= KVLEN) { sacc[nt][1] = -1e30f; sacc[nt][3] = -1e30f; }
            }
        }

        float mx0 = -1e30f, mx1 = -1e30f;
        #pragma unroll
        for (int nt = 0; nt < 8; nt++) {
            mx0 = fmaxf(mx0, fmaxf(sacc[nt][0], sacc[nt][1]));
            mx1 = fmaxf(mx1, fmaxf(sacc[nt][2], sacc[nt][3]));
        }
        mx0 = fmaxf(mx0, __shfl_xor_sync(0xffffffffu, mx0, 1));
        mx0 = fmaxf(mx0, __shfl_xor_sync(0xffffffffu, mx0, 2));
        mx1 = fmaxf(mx1, __shfl_xor_sync(0xffffffffu, mx1, 1));
        mx1 = fmaxf(mx1, __shfl_xor_sync(0xffffffffu, mx1, 2));
        float mn0 = fmaxf(m0r, mx0), mn1 = fmaxf(m1r, mx1);
        float f0 = __expf(m0r - mn0), f1 = __expf(m1r - mn1);
        float s0 = 0.f, s1 = 0.f;
        int prow = warp * 16 + lr;
        #pragma unroll
        for (int nt = 0; nt < 8; nt++) {
            float p00 = __expf(sacc[nt][0] - mn0);
            float p01 = __expf(sacc[nt][1] - mn0);
            float p10 = __expf(sacc[nt][2] - mn1);
            float p11 = __expf(sacc[nt][3] - mn1);
            s0 += p00 + p01; s1 += p10 + p11;
            Ps[(prow    ) * PS_ST + nt * 8 + 2 * lc    ] = p00;
            Ps[(prow    ) * PS_ST + nt * 8 + 2 * lc + 1] = p01;
            Ps[(prow + 8) * PS_ST + nt * 8 + 2 * lc    ] = p10;
            Ps[(prow + 8) * PS_ST + nt * 8 + 2 * lc + 1] = p11;
            oacc[nt][0] *= f0; oacc[nt][1] *= f0;
            oacc[nt][2] *= f1; oacc[nt][3] *= f1;
        }
        s0 += __shfl_xor_sync(0xffffffffu, s0, 1);
        s0 += __shfl_xor_sync(0xffffffffu, s0, 2);
        s1 += __shfl_xor_sync(0xffffffffu, s1, 1);
        s1 += __shfl_xor_sync(0xffffffffu, s1, 2);
        l0r = l0r * f0 + s0; l1r = l1r * f1 + s1;
        m0r = mn0; m1r = mn1;
        __syncthreads();

        #pragma unroll
        for (int ks = 0; ks < 8; ks++) {
            uint32_t a0 = __float_as_uint(Ps[(prow    ) * PS_ST + ks * 8 + lc    ]);
            uint32_t a1 = __float_as_uint(Ps[(prow + 8) * PS_ST + ks * 8 + lc    ]);
            uint32_t a2 = __float_as_uint(Ps[(prow    ) * PS_ST + ks * 8 + lc + 4]);
            uint32_t a3 = __float_as_uint(Ps[(prow + 8) * PS_ST + ks * 8 + lc + 4]);
            #pragma unroll
            for (int nt = 0; nt < 8; nt++) {
                uint32_t b0 = __float_as_uint(Vt[(ks * 8 + lc    ) * VS_ST + nt * 8 + lr]);
                uint32_t b1 = __float_as_uint(Vt[(ks * 8 + lc + 4) * VS_ST + nt * 8 + lr]);
                MMA_TF32(oacc[nt], a0, a1, a2, a3, b0, b1);
            }
        }
    }

    float inv0 = 1.f / l0r, inv1 = 1.f / l1r;
    float* Ob = O + (size_t)(b * NHW) * ND + hh * HDIM;
    #pragma unroll
    for (int nt = 0; nt < 8; nt++) {
        int col = nt * 8 + 2 * lc;
        Ob[(size_t)(qrow0 + lr    ) * ND + col    ] = oacc[nt][0] * inv0;
        Ob[(size_t)(qrow0 + lr    ) * ND + col + 1] = oacc[nt][1] * inv0;
        Ob[(size_t)(qrow0 + lr + 8) * ND + col    ] = oacc[nt][2] * inv1;
        Ob[(size_t)(qrow0 + lr + 8) * ND + col + 1] = oacc[nt][3] * inv1;
    }
}

// ================= small kernels =================
__device__ __forceinline__ float blk_reduce(float v, int is_max) {
    __shared__ float sh[33];
    int lane = threadIdx.x & 31, w = threadIdx.x >> 5;
    #pragma unroll
    for (int o = 16; o; o >>= 1) {
        float t = __shfl_down_sync(0xffffffffu, v, o);
        v = is_max ? fmaxf(v, t) : v + t;
    }
    if (!lane) sh[w] = v;
    __syncthreads();
    int nw = blockDim.x >> 5;
    v = (threadIdx.x < nw) ? sh[threadIdx.x] : (is_max ? -1e30f : 0.0f);
    if (w == 0) {
        #pragma unroll
        for (int o = 16; o; o >>= 1) {
            float t = __shfl_down_sync(0xffffffffu, v, o);
            v = is_max ? fmaxf(v, t) : v + t;
        }
        if (threadIdx.x == 0) sh[32] = v;
    }
    __syncthreads();
    float r = sh[32];
    __syncthreads();
    return r;
}

// fused dual sum reduce (one smem round)
__device__ __forceinline__ float2 blk_reduce2(float a, float b) {
    __shared__ float sha[9], shb[9];
    int lane = threadIdx.x & 31, w = threadIdx.x >> 5;
    #pragma unroll
    for (int o = 16; o; o >>= 1) {
        a += __shfl_down_sync(0xffffffffu, a, o);
        b += __shfl_down_sync(0xffffffffu, b, o);
    }
    if (!lane) { sha[w] = a; shb[w] = b; }
    __syncthreads();
    if (threadIdx.x == 0) {
        int nw = blockDim.x >> 5;
        float ta = 0.f, tb = 0.f;
        for (int i = 0; i < nw; i++) { ta += sha[i]; tb += shb[i]; }
        sha[8] = ta; shb[8] = tb;
    }
    __syncthreads();
    float2 r = make_float2(sha[8], shb[8]);
    __syncthreads();
    return r;
}

__global__ void gn_stats_k(const float* __restrict__ x, float* __restrict__ mean,
                           float* __restrict__ rstd) {
    int bg = blockIdx.x;
    const float* p = x + (size_t)bg * 16384;
    float s = 0.f, s2 = 0.f;
    for (int i = threadIdx.x; i < 16384; i += 256) {
        float v = p[i];
        s += v; s2 += v * v;
    }
    float2 r = blk_reduce2(s, s2);
    if (threadIdx.x == 0) {
        float mu  = r.x * (1.f / 16384.f);
        float var = r.y * (1.f / 16384.f) - mu * mu;
        mean[bg] = mu;
        rstd[bg] = rsqrtf(var + EPSV);
    }
}

__global__ void gn_apply_k(const float* __restrict__ x, const float* __restrict__ gamma,
                           const float* __restrict__ beta, const float* __restrict__ mean,
                           const float* __restrict__ rstd, float* __restrict__ xn) {
    __shared__ float tile[32][33];
    int b = blockIdx.z;
    int c0 = blockIdx.y * 32, hw0 = blockIdx.x * 32;
    int c = c0 + threadIdx.y, hw = hw0 + threadIdx.x;
    float v = x[((size_t)b * NC + c) * NHW + hw];
    int grp = c >> 4;
    float mu = mean[b * 32 + grp], rs = rstd[b * 32 + grp];
    tile[threadIdx.y][threadIdx.x] = (v - mu) * rs * gamma[c] + beta[c];
    __syncthreads();
    xn[((size_t)b * NHW + hw0 + threadIdx.y) * ND + c0 + threadIdx.x] =
        tile[threadIdx.x][threadIdx.y];
}

__global__ void ln_k(const float* __restrict__ x, const float* __restrict__ g,
                     const float* __restrict__ b, float* __restrict__ y) {
    size_t row = blockIdx.x;
    const float* xr = x + row * ND;
    float* yr = y + row * ND;
    int t = threadIdx.x;
    float v0 = xr[t], v1 = xr[t + 256];
    float2 r = blk_reduce2(v0 + v1, v0 * v0 + v1 * v1);
    float mu = r.x * (1.f / ND);
    float rs = rsqrtf(r.y * (1.f / ND) - mu * mu + EPSV);
    yr[t]       = (v0 - mu) * rs * g[t]       + b[t];
    yr[t + 256] = (v1 - mu) * rs * g[t + 256] + b[t + 256];
}

__global__ void out_add_k(const float* __restrict__ t, const float* __restrict__ x_in,
                          float* __restrict__ out) {
    __shared__ float tile[32][33];
    int b = blockIdx.z;
    int c0 = blockIdx.x * 32, hw0 = blockIdx.y * 32;
    tile[threadIdx.y][threadIdx.x] =
        t[((size_t)b * NHW + hw0 + threadIdx.y) * ND + c0 + threadIdx.x];
    __syncthreads();
    size_t o = ((size_t)b * NC + c0 + threadIdx.y) * NHW + hw0 + threadIdx.x;
    out[o] = tile[threadIdx.x][threadIdx.y] + x_in[o];
}

// ================= host =================
template<int BN, bool TRANSB>
static void tcl(const float* A, const float* B, float* C,
                int M, int N, int K, int lda, int ldb, int ldc,
                const float* bias, const float* res, int gelu,
                int batch = 1, int bh = 1,
                long long sA1 = 0, long long sA2 = 0,
                long long sB1 = 0, long long sB2 = 0,
                long long sC1 = 0, long long sC2 = 0) {
    constexpr int AW = 128 * 36;
    constexpr int BW = TRANSB ? BN * 36 : 32 * (BN + 8);
    int smem = 3 * (AW + BW) * 4;
    static bool attr_set = false;
    if (!attr_set) {
        cudaFuncSetAttribute(mma_gemm_k<BN, TRANSB>,
                             cudaFuncAttributeMaxDynamicSharedMemorySize, smem);
        attr_set = true;
    }
    dim3 grid((N + BN - 1) / BN, (M + 127) / 128, batch);
    mma_gemm_k<BN, TRANSB><<<grid, 256, smem>>>(A, B, C, M, N, K, lda, ldb, ldc, bh,
                                                sA1, sA2, sB1, sB2, sC1, sC2,
                                                bias, res, gelu);
}

extern "C" void kernel_launch(void* const* d_in, const int* in_sizes, int n_in,
                              void* d_out, int out_size) {
    const float* x      = (const float*)d_in[0];
    const float* ctx    = (const float*)d_in[1];
    const float* gn_g   = (const float*)d_in[2];
    const float* gn_b   = (const float*)d_in[3];
    const float* pin_w  = (const float*)d_in[4];
    const float* pin_b  = (const float*)d_in[5];
    const float* ln1_g  = (const float*)d_in[6];
    const float* ln1_b  = (const float*)d_in[7];
    const float* q1_w   = (const float*)d_in[8];
    const float* k1_w   = (const float*)d_in[9];
    const float* v1_w   = (const float*)d_in[10];
    const float* o1_w   = (const float*)d_in[11];
    const float* o1_b   = (const float*)d_in[12];
    const float* ln2_g  = (const float*)d_in[13];
    const float* ln2_b  = (const float*)d_in[14];
    const float* q2_w   = (const float*)d_in[15];
    const float* k2_w   = (const float*)d_in[16];
    const float* v2_w   = (const float*)d_in[17];
    const float* o2_w   = (const float*)d_in[18];
    const float* o2_b   = (const float*)d_in[19];
    const float* ln3_g  = (const float*)d_in[20];
    const float* ln3_b  = (const float*)d_in[21];
    const float* ff1_w  = (const float*)d_in[22];
    const float* ff1_b  = (const float*)d_in[23];
    const float* ff2_w  = (const float*)d_in[24];
    const float* ff2_b  = (const float*)d_in[25];
    const float* pout_w = (const float*)d_in[26];
    const float* pout_b = (const float*)d_in[27];
    float* out = (float*)d_out;

    float *xn, *h, *hn, *q, *k, *v, *ao, *ff, *gmean, *grstd;
    cudaGetSymbolAddress((void**)&xn,    g_xn);
    cudaGetSymbolAddress((void**)&h,     g_h);
    cudaGetSymbolAddress((void**)&hn,    g_hn);
    cudaGetSymbolAddress((void**)&q,     g_q);
    cudaGetSymbolAddress((void**)&k,     g_k);
    cudaGetSymbolAddress((void**)&v,     g_v);
    cudaGetSymbolAddress((void**)&ao,    g_ao);
    cudaGetSymbolAddress((void**)&ff,    g_ff);
    cudaGetSymbolAddress((void**)&gmean, g_gmean);
    cudaGetSymbolAddress((void**)&grstd, g_grstd);

    dim3 t32(32, 32);

    static bool fa_attr = false;
    if (!fa_attr) {
        cudaFuncSetAttribute(flash_attn_k<16, 1024, 1024>,
                             cudaFuncAttributeMaxDynamicSharedMemorySize, FA_SMEM);
        cudaFuncSetAttribute(flash_attn_k<2, 77, 77>,
                             cudaFuncAttributeMaxDynamicSharedMemorySize, FA_SMEM);
        fa_attr = true;
    }

    // 1) GroupNorm + transpose to token-major
    gn_stats_k<<<NB * 32, 256>>>(x, gmean, grstd);
    gn_apply_k<<<dim3(NHW / 32, NC / 32, NB), t32>>>(x, gn_g, gn_b, gmean, grstd, xn);

    // 2) proj_in
    tcl<128, false>(xn, pin_w, h, NTOK, ND, ND, ND, ND, ND, pin_b, nullptr, 0);

    // 3) self-attention (fused flash)
    ln_k<<<NTOK, 256>>>(h, ln1_g, ln1_b, hn);
    tcl<128, false>(hn, q1_w, q, NTOK, ND, ND, ND, ND, ND, nullptr, nullptr, 0);
    tcl<128, false>(hn, k1_w, k, NTOK, ND, ND, ND, ND, ND, nullptr, nullptr, 0);
    tcl<128, false>(hn, v1_w, v, NTOK, ND, ND, ND, ND, ND, nullptr, nullptr, 0);
    flash_attn_k<16, 1024, 1024><<<dim3(NHW / 128, NB * NHEAD), 256, FA_SMEM>>>(q, k, v, ao);
    tcl<128, false>(ao, o1_w, h, NTOK, ND, ND, ND, ND, ND, o1_b, h, 0);

    // 4) cross-attention (fused flash, KV len 77)
    ln_k<<<NTOK, 256>>>(h, ln2_g, ln2_b, hn);
    tcl<128, false>(hn, q2_w, q, NTOK, ND, ND, ND, ND, ND, nullptr, nullptr, 0);
    tcl<128, false>(ctx, k2_w, k, NB * NL, ND, NDC, NDC, ND, ND, nullptr, nullptr, 0);
    tcl<128, false>(ctx, v2_w, v, NB * NL, ND, NDC, NDC, ND, ND, nullptr, nullptr, 0);
    flash_attn_k<2, 77, 77><<<dim3(NHW / 128, NB * NHEAD), 256, FA_SMEM>>>(q, k, v, ao);
    tcl<128, false>(ao, o2_w, h, NTOK, ND, ND, ND, ND, ND, o2_b, h, 0);

    // 5) feed-forward
    ln_k<<<NTOK, 256>>>(h, ln3_g, ln3_b, hn);
    tcl<128, false>(hn, ff1_w, ff, NTOK, NFF, ND, ND, NFF, NFF, ff1_b, nullptr, 1);
    tcl<128, false>(ff, ff2_w, h, NTOK, ND, NFF, NFF, ND, ND, ff2_b, h, 0);

    // 6) proj_out + input residual
    tcl<128, false>(h, pout_w, ao, NTOK, NC, ND, ND, NC, NC, pout_b, nullptr, 0);
    out_add_k<<<dim3(NC / 32, NHW / 32, NB), t32>>>(ao, x, out);
}

// round 13
// speedup vs baseline: 9.7999x; 1.6843x over previous
#include <cuda_runtime.h>
#include <cuda_fp16.h>
#include <math.h>
#include <stdint.h>

// ---------------- problem constants ----------------
#define NB    8
#define NC    512
#define NHW   1024
#define NTOK  8192
#define ND    512
#define NDC   768
#define NL    77
#define NHEAD 8
#define HDIM  64
#define NFF   2048
#define EPSV  1e-5f

// ---------------- scratch ----------------
__device__ float  g_h  [(size_t)NTOK*ND];
__device__ float  g_po [(size_t)NTOK*ND];
__device__ __half g_xn [(size_t)NTOK*ND];
__device__ __half g_hn [(size_t)NTOK*ND];
__device__ __half g_h16[(size_t)NTOK*ND];
__device__ __half g_q  [(size_t)NTOK*ND];
__device__ __half g_k  [(size_t)NTOK*ND];
__device__ __half g_v  [(size_t)NTOK*ND];
__device__ __half g_ao [(size_t)NTOK*ND];
__device__ __half g_ff [(size_t)NTOK*NFF];
__device__ __half g_w16[4980736];
__device__ __half g_ctx16[616*768];
__device__ float  g_gmean[NB*32];
__device__ float  g_grstd[NB*32];

// w16 pool offsets (halves)
#define WT_PIN  0
#define WT_Q1   262144
#define WT_K1   524288
#define WT_V1   786432
#define WT_O1   1048576
#define WT_Q2   1310720
#define WT_O2   1572864
#define WT_POUT 1835008
#define WT_K2   2097152
#define WT_V2   2490368
#define WT_FF1  2883584
#define WT_FF2  3932160

// ---------------- PTX helpers ----------------
__device__ __forceinline__ uint32_t smem_u32(const void* p) {
    uint32_t a;
    asm("{ .reg .u64 t; cvta.to.shared.u64 t, %1; cvt.u32.u64 %0, t; }" : "=r"(a) : "l"(p));
    return a;
}
__device__ __forceinline__ uint32_t h2_u32(__half2 h) {
    union { __half2 h; uint32_t u; } c;
    c.h = h;
    return c.u;
}
__device__ __forceinline__ void cp16(uint32_t dst, const void* src, bool pred) {
    int sz = pred ? 16 : 0;
    asm volatile("cp.async.cg.shared.global [%0], [%1], 16, %2;\n" :: "r"(dst), "l"(src), "r"(sz));
}
__device__ __forceinline__ void ldsm4(uint32_t& r0, uint32_t& r1, uint32_t& r2, uint32_t& r3,
                                      uint32_t a) {
    asm volatile("ldmatrix.sync.aligned.m8n8.x4.shared.b16 {%0,%1,%2,%3}, [%4];"
                 : "=r"(r0), "=r"(r1), "=r"(r2), "=r"(r3) : "r"(a));
}
__device__ __forceinline__ void ldsm4t(uint32_t& r0, uint32_t& r1, uint32_t& r2, uint32_t& r3,
                                       uint32_t a) {
    asm volatile("ldmatrix.sync.aligned.m8n8.x4.trans.shared.b16 {%0,%1,%2,%3}, [%4];"
                 : "=r"(r0), "=r"(r1), "=r"(r2), "=r"(r3) : "r"(a));
}
#define MMA_F16(acc, a0,a1,a2,a3, b0,b1) \
    asm volatile("mma.sync.aligned.m16n8k16.row.col.f32.f16.f16.f32 " \
        "{%0,%1,%2,%3}, {%4,%5,%6,%7}, {%8,%9}, {%0,%1,%2,%3};" \
        : "+f"((acc)[0]), "+f"((acc)[1]), "+f"((acc)[2]), "+f"((acc)[3]) \
        : "r"(a0), "r"(a1), "r"(a2), "r"(a3), "r"(b0), "r"(b1))

// ================= fp16 warp-MMA GEMM =====================================
// C = A[M,K] @ B[K,N] (+bias, +res, gelu). fp16 in, fp32 accumulate.
// 128x128 CTA tile, K-tile 32, 256 thr (8 warps 4x2), 3-stage cp.async.
// OUTMODE: 0=f32 C, 1=f16 C16, 2=both.
#define SAH 40                  // A smem row stride (halves)
#define SBH 136                 // B smem row stride (halves)
#define AH  (128*SAH)           // 5120 halves
#define BH  (32*SBH)            // 4352 halves
#define STH (AH + BH)
#define G_SMEM (3*STH*2)

template<int OUTMODE>
__global__ __launch_bounds__(256, 2)
void hgemm_k(const __half* __restrict__ A, const __half* __restrict__ Bm,
             float* __restrict__ C, __half* __restrict__ C16,
             int M, int K, int lda, int ldb, int ldc,
             const float* __restrict__ bias, const float* __restrict__ res,
             int gelu, float oscale) {
    extern __shared__ __half smh[];

    int tid = threadIdx.x;
    int warp = tid >> 5, lane = tid & 31;
    int wm = warp & 3, wn = warp >> 2;
    int lr = lane >> 2, lc = lane & 3;
    int l8 = lane & 7, grp = lane >> 3;
    int m0 = blockIdx.y * 128, n0 = blockIdx.x * 128;

    float acc[2][8][4];
    #pragma unroll
    for (int i = 0; i < 2; i++)
        #pragma unroll
        for (int j = 0; j < 8; j++)
            #pragma unroll
            for (int l = 0; l < 4; l++) acc[i][j][l] = 0.f;

    int KT = K >> 5;

    auto load_tile = [&](int st, int kt) {
        __half* As = smh + st * STH;
        __half* Bs = As + AH;
        int k0 = kt << 5;
        #pragma unroll
        for (int i = 0; i < 2; i++) {      // A: 128 rows x 4 chunks (8 halves)
            int idx = tid + i * 256;
            int r = idx >> 2, c = idx & 3;
            int gm = m0 + r;
            int gs = gm < M ? gm : M - 1;
            cp16(smem_u32(As + r * SAH + c * 8),
                 A + (size_t)gs * lda + k0 + c * 8, gm < M);
        }
        #pragma unroll
        for (int i = 0; i < 2; i++) {      // B: 32 k-rows x 16 chunks
            int idx = tid + i * 256;
            int r = idx >> 4, c = idx & 15;
            cp16(smem_u32(Bs + r * SBH + c * 8),
                 Bm + (size_t)(k0 + r) * ldb + n0 + c * 8, true);
        }
        asm volatile("cp.async.commit_group;\n" ::: "memory");
    };

    load_tile(0, 0);
    load_tile(1, 1 < KT ? 1 : 0);

    // ldmatrix address offsets (bytes), relative to stage base
    uint32_t aoff[2], boff[4];
    #pragma unroll
    for (int mt = 0; mt < 2; mt++) {
        int arow = wm * 32 + mt * 16 + (grp & 1) * 8 + l8;
        aoff[mt] = (arow * SAH + (grp >> 1) * 8) * 2;
    }
    #pragma unroll
    for (int nf2 = 0; nf2 < 4; nf2++) {
        int brow = (grp & 1) * 8 + l8;                      // k
        int bcol = wn * 64 + nf2 * 16 + (grp >> 1) * 8;     // n
        boff[nf2] = (AH + brow * SBH + bcol) * 2;
    }

    for (int kt = 0; kt < KT; kt++) {
        if (kt + 1 < KT) { asm volatile("cp.async.wait_group 1;\n" ::: "memory"); }
        else             { asm volatile("cp.async.wait_group 0;\n" ::: "memory"); }
        __syncthreads();
        if (kt + 2 < KT) load_tile((kt + 2) % 3, kt + 2);

        uint32_t sbase = smem_u32(smh + (kt % 3) * STH);
        #pragma unroll
        for (int s16 = 0; s16 < 2; s16++) {
            uint32_t ka = sbase + s16 * 32;         // ks16*2 bytes
            uint32_t kb = sbase + s16 * 16 * SBH * 2;
            uint32_t a[2][4];
            ldsm4(a[0][0], a[0][1], a[0][2], a[0][3], ka + aoff[0]);
            ldsm4(a[1][0], a[1][1], a[1][2], a[1][3], ka + aoff[1]);
            uint32_t bq[8][2];
            #pragma unroll
            for (int nf2 = 0; nf2 < 4; nf2++) {
                uint32_t r0, r1, r2, r3;
                ldsm4t(r0, r1, r2, r3, kb + boff[nf2]);
                bq[nf2 * 2][0] = r0;     bq[nf2 * 2][1] = r1;
                bq[nf2 * 2 + 1][0] = r2; bq[nf2 * 2 + 1][1] = r3;
            }
            #pragma unroll
            for (int mt = 0; mt < 2; mt++)
                #pragma unroll
                for (int nt = 0; nt < 8; nt++)
                    MMA_F16(acc[mt][nt], a[mt][0], a[mt][1], a[mt][2], a[mt][3],
                            bq[nt][0], bq[nt][1]);
        }
    }

    // epilogue
    #pragma unroll
    for (int mt = 0; mt < 2; mt++) {
        #pragma unroll
        for (int nt = 0; nt < 8; nt++) {
            int row0 = m0 + wm * 32 + mt * 16 + lr;
            int col0 = n0 + wn * 64 + nt * 8 + 2 * lc;
            #pragma unroll
            for (int hf = 0; hf < 2; hf++) {
                int gm = row0 + hf * 8;
                if (gm >= M) continue;
                float r0 = acc[mt][nt][hf * 2], r1 = acc[mt][nt][hf * 2 + 1];
                if (bias) { r0 += bias[col0]; r1 += bias[col0 + 1]; }
                if (res) {
                    r0 += res[(size_t)gm * ldc + col0];
                    r1 += res[(size_t)gm * ldc + col0 + 1];
                }
                if (gelu) {
                    r0 = 0.5f * r0 * (1.f + erff(r0 * 0.70710678118654752f));
                    r1 = 0.5f * r1 * (1.f + erff(r1 * 0.70710678118654752f));
                }
                r0 *= oscale; r1 *= oscale;
                if (OUTMODE == 0 || OUTMODE == 2) {
                    C[(size_t)gm * ldc + col0] = r0;
                    C[(size_t)gm * ldc + col0 + 1] = r1;
                }
                if (OUTMODE >= 1)
                    *(__half2*)&C16[(size_t)gm * ldc + col0] = __floats2half2_rn(r0, r1);
            }
        }
    }
}

// ================= fused flash attention (fp16) ===========================
#define FS_ST 72                 // K/V/P smem row stride (halves)
#define KV_STG (64*FS_ST)
#define FA_SMEM ((2*KV_STG + 2*KV_STG + 128*FS_ST) * 2)

template<int NT, int KVLEN, int KVTOK>
__global__ __launch_bounds__(256, 2)
void flash_attn_k(const __half* __restrict__ Q, const __half* __restrict__ K,
                  const __half* __restrict__ V, __half* __restrict__ O) {
    constexpr bool MASK = (KVLEN & 63) != 0;
    extern __shared__ __half smh[];
    __half* Ks = smh;
    __half* Vs = smh + 2 * KV_STG;
    __half* Ps = smh + 4 * KV_STG;

    int tid = threadIdx.x, warp = tid >> 5, lane = tid & 31;
    int lr = lane >> 2, lc = lane & 3;
    int l8 = lane & 7, grp = lane >> 3;
    int bq = blockIdx.x;
    int bh = blockIdx.y;
    int b = bh >> 3, hh = bh & 7;

    const __half* Qb = Q + (size_t)(b * NHW) * ND + hh * HDIM;
    const __half* Kb = K + (size_t)(b * KVTOK) * ND + hh * HDIM;
    const __half* Vb = V + (size_t)(b * KVTOK) * ND + hh * HDIM;
    int qrow0 = bq * 128 + warp * 16;

    // Q fragments (scale already folded into q projection)
    uint32_t qf[4][4];
    {
        const uint32_t* q0 = (const uint32_t*)(Qb + (size_t)(qrow0 + lr    ) * ND);
        const uint32_t* q1 = (const uint32_t*)(Qb + (size_t)(qrow0 + lr + 8) * ND);
        #pragma unroll
        for (int kf = 0; kf < 4; kf++) {
            qf[kf][0] = q0[kf * 8 + lc];
            qf[kf][1] = q1[kf * 8 + lc];
            qf[kf][2] = q0[kf * 8 + 4 + lc];
            qf[kf][3] = q1[kf * 8 + 4 + lc];
        }
    }

    float oacc[8][4];
    #pragma unroll
    for (int i = 0; i < 8; i++)
        #pragma unroll
        for (int j = 0; j < 4; j++) oacc[i][j] = 0.f;
    float m0r = -1e30f, m1r = -1e30f, l0r = 0.f, l1r = 0.f;

    auto load_kv = [&](int st, int j) {
        int t0 = j * 64;
        #pragma unroll
        for (int i = 0; i < 2; i++) {       // 64 rows x 8 chunks each for K and V
            int idx = tid + i * 256;
            int r = idx >> 3, c = idx & 7;
            bool ok = (t0 + r) < KVLEN;
            cp16(smem_u32(Ks + st * KV_STG + r * FS_ST + c * 8),
                 Kb + (size_t)(t0 + r) * ND + c * 8, ok);
        }
        #pragma unroll
        for (int i = 0; i < 2; i++) {
            int idx = tid + i * 256;
            int r = idx >> 3, c = idx & 7;
            bool ok = (t0 + r) < KVLEN;
            cp16(smem_u32(Vs + st * KV_STG + r * FS_ST + c * 8),
                 Vb + (size_t)(t0 + r) * ND + c * 8, ok);
        }
        asm volatile("cp.async.commit_group;\n" ::: "memory");
    };

    load_kv(0, 0);
    #pragma unroll 1
    for (int j = 0; j < NT; j++) {
        int st = j & 1;
        __syncthreads();
        if (j + 1 < NT) {
            load_kv(st ^ 1, j + 1);
            asm volatile("cp.async.wait_group 1;\n" ::: "memory");
        } else {
            asm volatile("cp.async.wait_group 0;\n" ::: "memory");
        }
        __syncthreads();
        uint32_t ktb = smem_u32(Ks + st * KV_STG);
        uint32_t vtb = smem_u32(Vs + st * KV_STG);

        // ---- S = Q @ K^T (16x64 per warp)
        float sacc[8][4];
        #pragma unroll
        for (int i = 0; i < 8; i++)
            #pragma unroll
            for (int l = 0; l < 4; l++) sacc[i][l] = 0.f;
        #pragma unroll
        for (int kf = 0; kf < 4; kf++) {
            #pragma unroll
            for (int nf2 = 0; nf2 < 4; nf2++) {
                int nrow = nf2 * 16 + (grp >> 1) * 8 + l8;
                int kcol = kf * 16 + (grp & 1) * 8;
                uint32_t r0, r1, r2, r3;
                ldsm4(r0, r1, r2, r3, ktb + (nrow * FS_ST + kcol) * 2);
                MMA_F16(sacc[nf2 * 2],     qf[kf][0], qf[kf][1], qf[kf][2], qf[kf][3], r0, r1);
                MMA_F16(sacc[nf2 * 2 + 1], qf[kf][0], qf[kf][1], qf[kf][2], qf[kf][3], r2, r3);
            }
        }

        if (MASK && j == NT - 1) {
            #pragma unroll
            for (int nt = 0; nt < 8; nt++) {
                int c0 = j * 64 + nt * 8 + 2 * lc;
                if (c0     >= KVLEN) { sacc[nt][0] = -1e30f; sacc[nt][2] = -1e30f; }
                if (c0 + 1 >= KVLEN) { sacc[nt][1] = -1e30f; sacc[nt][3] = -1e30f; }
            }
        }

        // ---- online softmax
        float mx0 = -1e30f, mx1 = -1e30f;
        #pragma unroll
        for (int nt = 0; nt < 8; nt++) {
            mx0 = fmaxf(mx0, fmaxf(sacc[nt][0], sacc[nt][1]));
            mx1 = fmaxf(mx1, fmaxf(sacc[nt][2], sacc[nt][3]));
        }
        mx0 = fmaxf(mx0, __shfl_xor_sync(0xffffffffu, mx0, 1));
        mx0 = fmaxf(mx0, __shfl_xor_sync(0xffffffffu, mx0, 2));
        mx1 = fmaxf(mx1, __shfl_xor_sync(0xffffffffu, mx1, 1));
        mx1 = fmaxf(mx1, __shfl_xor_sync(0xffffffffu, mx1, 2));
        float mn0 = fmaxf(m0r, mx0), mn1 = fmaxf(m1r, mx1);
        float f0 = __expf(m0r - mn0), f1 = __expf(m1r - mn1);
        float s0 = 0.f, s1 = 0.f;
        int prow = warp * 16 + lr;
        uint32_t* Ps32 = (uint32_t*)Ps;
        #pragma unroll
        for (int nt = 0; nt < 8; nt++) {
            float p00 = __expf(sacc[nt][0] - mn0);
            float p01 = __expf(sacc[nt][1] - mn0);
            float p10 = __expf(sacc[nt][2] - mn1);
            float p11 = __expf(sacc[nt][3] - mn1);
            s0 += p00 + p01; s1 += p10 + p11;
            Ps32[(prow    ) * (FS_ST / 2) + nt * 4 + lc] =
                h2_u32(__floats2half2_rn(p00, p01));
            Ps32[(prow + 8) * (FS_ST / 2) + nt * 4 + lc] =
                h2_u32(__floats2half2_rn(p10, p11));
            oacc[nt][0] *= f0; oacc[nt][1] *= f0;
            oacc[nt][2] *= f1; oacc[nt][3] *= f1;
        }
        s0 += __shfl_xor_sync(0xffffffffu, s0, 1);
        s0 += __shfl_xor_sync(0xffffffffu, s0, 2);
        s1 += __shfl_xor_sync(0xffffffffu, s1, 1);
        s1 += __shfl_xor_sync(0xffffffffu, s1, 2);
        l0r = l0r * f0 + s0; l1r = l1r * f1 + s1;
        m0r = mn0; m1r = mn1;
        // no cross-warp sync needed: P rows are warp-private

        // ---- O += P @ V
        uint32_t psb = smem_u32(Ps);
        #pragma unroll
        for (int kf = 0; kf < 4; kf++) {
            uint32_t pa[4];
            {
                int arow = warp * 16 + (grp & 1) * 8 + l8;
                int acol = kf * 16 + (grp >> 1) * 8;
                ldsm4(pa[0], pa[1], pa[2], pa[3], psb + (arow * FS_ST + acol) * 2);
            }
            #pragma unroll
            for (int nf2 = 0; nf2 < 4; nf2++) {
                int krow = kf * 16 + (grp & 1) * 8 + l8;
                int ncol = nf2 * 16 + (grp >> 1) * 8;
                uint32_t r0, r1, r2, r3;
                ldsm4t(r0, r1, r2, r3, vtb + (krow * FS_ST + ncol) * 2);
                MMA_F16(oacc[nf2 * 2],     pa[0], pa[1], pa[2], pa[3], r0, r1);
                MMA_F16(oacc[nf2 * 2 + 1], pa[0], pa[1], pa[2], pa[3], r2, r3);
            }
        }
    }

    float inv0 = 1.f / l0r, inv1 = 1.f / l1r;
    __half* Ob = O + (size_t)(b * NHW) * ND + hh * HDIM;
    #pragma unroll
    for (int nt = 0; nt < 8; nt++) {
        int col = nt * 8 + 2 * lc;
        *(__half2*)&Ob[(size_t)(qrow0 + lr    ) * ND + col] =
            __floats2half2_rn(oacc[nt][0] * inv0, oacc[nt][1] * inv0);
        *(__half2*)&Ob[(size_t)(qrow0 + lr + 8) * ND + col] =
            __floats2half2_rn(oacc[nt][2] * inv1, oacc[nt][3] * inv1);
    }
}

// ================= small kernels =================
__device__ __forceinline__ float2 blk_reduce2(float a, float b) {
    __shared__ float sha[9], shb[9];
    int lane = threadIdx.x & 31, w = threadIdx.x >> 5;
    #pragma unroll
    for (int o = 16; o; o >>= 1) {
        a += __shfl_down_sync(0xffffffffu, a, o);
        b += __shfl_down_sync(0xffffffffu, b, o);
    }
    if (!lane) { sha[w] = a; shb[w] = b; }
    __syncthreads();
    if (threadIdx.x == 0) {
        int nw = blockDim.x >> 5;
        float ta = 0.f, tb = 0.f;
        for (int i = 0; i < nw; i++) { ta += sha[i]; tb += shb[i]; }
        sha[8] = ta; shb[8] = tb;
    }
    __syncthreads();
    float2 r = make_float2(sha[8], shb[8]);
    __syncthreads();
    return r;
}

struct CvtSegs {
    const float* src[13];
    __half* dst[13];
    int n[13];
};
__global__ void cvt_k(CvtSegs cs) {
    int seg = blockIdx.y;
    int n = cs.n[seg];
    const float* s = cs.src[seg];
    __half* d = cs.dst[seg];
    for (int i = blockIdx.x * blockDim.x + threadIdx.x; i < n; i += gridDim.x * blockDim.x)
        d[i] = __float2half(s[i]);
}

__global__ void gn_stats_k(const float* __restrict__ x, float* __restrict__ mean,
                           float* __restrict__ rstd) {
    int bg = blockIdx.x;
    const float* p = x + (size_t)bg * 16384;
    float s = 0.f, s2 = 0.f;
    for (int i = threadIdx.x; i < 16384; i += 256) {
        float v = p[i];
        s += v; s2 += v * v;
    }
    float2 r = blk_reduce2(s, s2);
    if (threadIdx.x == 0) {
        float mu  = r.x * (1.f / 16384.f);
        float var = r.y * (1.f / 16384.f) - mu * mu;
        mean[bg] = mu;
        rstd[bg] = rsqrtf(var + EPSV);
    }
}

__global__ void gn_apply_k(const float* __restrict__ x, const float* __restrict__ gamma,
                           const float* __restrict__ beta, const float* __restrict__ mean,
                           const float* __restrict__ rstd, __half* __restrict__ xn) {
    __shared__ float tile[32][33];
    int b = blockIdx.z;
    int c0 = blockIdx.y * 32, hw0 = blockIdx.x * 32;
    int c = c0 + threadIdx.y, hw = hw0 + threadIdx.x;
    float v = x[((size_t)b * NC + c) * NHW + hw];
    int grp = c >> 4;
    float mu = mean[b * 32 + grp], rs = rstd[b * 32 + grp];
    tile[threadIdx.y][threadIdx.x] = (v - mu) * rs * gamma[c] + beta[c];
    __syncthreads();
    xn[((size_t)b * NHW + hw0 + threadIdx.y) * ND + c0 + threadIdx.x] =
        __float2half(tile[threadIdx.x][threadIdx.y]);
}

__global__ void ln_k(const float* __restrict__ x, const float* __restrict__ g,
                     const float* __restrict__ b, __half* __restrict__ y) {
    size_t row = blockIdx.x;
    const float2* xr = (const float2*)(x + row * ND);
    int t = threadIdx.x;
    float2 v = xr[t];
    float2 r = blk_reduce2(v.x + v.y, v.x * v.x + v.y * v.y);
    float mu = r.x * (1.f / ND);
    float rs = rsqrtf(r.y * (1.f / ND) - mu * mu + EPSV);
    float n0 = (v.x - mu) * rs * g[2 * t]     + b[2 * t];
    float n1 = (v.y - mu) * rs * g[2 * t + 1] + b[2 * t + 1];
    ((__half2*)(y + row * ND))[t] = __floats2half2_rn(n0, n1);
}

__global__ void out_add_k(const float* __restrict__ t, const float* __restrict__ x_in,
                          float* __restrict__ out) {
    __shared__ float tile[32][33];
    int b = blockIdx.z;
    int c0 = blockIdx.x * 32, hw0 = blockIdx.y * 32;
    tile[threadIdx.y][threadIdx.x] =
        t[((size_t)b * NHW + hw0 + threadIdx.y) * ND + c0 + threadIdx.x];
    __syncthreads();
    size_t o = ((size_t)b * NC + c0 + threadIdx.y) * NHW + hw0 + threadIdx.x;
    out[o] = tile[threadIdx.x][threadIdx.y] + x_in[o];
}

// ================= host =================
template<int OUTMODE>
static void hg(const __half* A, const __half* B, float* C, __half* C16,
               int M, int N, int K, int lda, int ldb, int ldc,
               const float* bias, const float* res, int gelu, float oscale = 1.f) {
    static bool attr_set = false;
    if (!attr_set) {
        cudaFuncSetAttribute(hgemm_k<OUTMODE>,
                             cudaFuncAttributeMaxDynamicSharedMemorySize, G_SMEM);
        attr_set = true;
    }
    dim3 grid(N / 128, (M + 127) / 128);
    hgemm_k<OUTMODE><<<grid, 256, G_SMEM>>>(A, B, C, C16, M, K, lda, ldb, ldc,
                                            bias, res, gelu, oscale);
}

extern "C" void kernel_launch(void* const* d_in, const int* in_sizes, int n_in,
                              void* d_out, int out_size) {
    const float* x      = (const float*)d_in[0];
    const float* ctx    = (const float*)d_in[1];
    const float* gn_g   = (const float*)d_in[2];
    const float* gn_b   = (const float*)d_in[3];
    const float* pin_w  = (const float*)d_in[4];
    const float* pin_b  = (const float*)d_in[5];
    const float* ln1_g  = (const float*)d_in[6];
    const float* ln1_b  = (const float*)d_in[7];
    const float* q1_w   = (const float*)d_in[8];
    const float* k1_w   = (const float*)d_in[9];
    const float* v1_w   = (const float*)d_in[10];
    const float* o1_w   = (const float*)d_in[11];
    const float* o1_b   = (const float*)d_in[12];
    const float* ln2_g  = (const float*)d_in[13];
    const float* ln2_b  = (const float*)d_in[14];
    const float* q2_w   = (const float*)d_in[15];
    const float* k2_w   = (const float*)d_in[16];
    const float* v2_w   = (const float*)d_in[17];
    const float* o2_w   = (const float*)d_in[18];
    const float* o2_b   = (const float*)d_in[19];
    const float* ln3_g  = (const float*)d_in[20];
    const float* ln3_b  = (const float*)d_in[21];
    const float* ff1_w  = (const float*)d_in[22];
    const float* ff1_b  = (const float*)d_in[23];
    const float* ff2_w  = (const float*)d_in[24];
    const float* ff2_b  = (const float*)d_in[25];
    const float* pout_w = (const float*)d_in[26];
    const float* pout_b = (const float*)d_in[27];
    float* out = (float*)d_out;

    float *h, *po, *gmean, *grstd;
    __half *xn, *hn, *h16, *q, *k, *v, *ao, *ff, *w16, *ctx16;
    cudaGetSymbolAddress((void**)&h,     g_h);
    cudaGetSymbolAddress((void**)&po,    g_po);
    cudaGetSymbolAddress((void**)&xn,    g_xn);
    cudaGetSymbolAddress((void**)&hn,    g_hn);
    cudaGetSymbolAddress((void**)&h16,   g_h16);
    cudaGetSymbolAddress((void**)&q,     g_q);
    cudaGetSymbolAddress((void**)&k,     g_k);
    cudaGetSymbolAddress((void**)&v,     g_v);
    cudaGetSymbolAddress((void**)&ao,    g_ao);
    cudaGetSymbolAddress((void**)&ff,    g_ff);
    cudaGetSymbolAddress((void**)&w16,   g_w16);
    cudaGetSymbolAddress((void**)&ctx16, g_ctx16);
    cudaGetSymbolAddress((void**)&gmean, g_gmean);
    cudaGetSymbolAddress((void**)&grstd, g_grstd);

    dim3 t32(32, 32);

    static bool fa_attr = false;
    if (!fa_attr) {
        cudaFuncSetAttribute(flash_attn_k<16, 1024, 1024>,
                             cudaFuncAttributeMaxDynamicSharedMemorySize, FA_SMEM);
        cudaFuncSetAttribute(flash_attn_k<2, 77, 77>,
                             cudaFuncAttributeMaxDynamicSharedMemorySize, FA_SMEM);
        fa_attr = true;
    }

    // 0) fp16 conversions (weights + ctx)
    {
        CvtSegs cs;
        const float* srcs[13] = {pin_w, q1_w, k1_w, v1_w, o1_w, q2_w, o2_w, pout_w,
                                 k2_w, v2_w, ff1_w, ff2_w, ctx};
        __half* dsts[13] = {w16 + WT_PIN, w16 + WT_Q1, w16 + WT_K1, w16 + WT_V1,
                            w16 + WT_O1, w16 + WT_Q2, w16 + WT_O2, w16 + WT_POUT,
                            w16 + WT_K2, w16 + WT_V2, w16 + WT_FF1, w16 + WT_FF2,
                            ctx16};
        int ns[13] = {262144, 262144, 262144, 262144, 262144, 262144, 262144, 262144,
                      393216, 393216, 1048576, 1048576, 473088};
        for (int i = 0; i < 13; i++) { cs.src[i] = srcs[i]; cs.dst[i] = dsts[i]; cs.n[i] = ns[i]; }
        cvt_k<<<dim3(512, 13), 256>>>(cs);
    }

    // 1) GroupNorm + transpose to token-major (fp16 out)
    gn_stats_k<<<NB * 32, 256>>>(x, gmean, grstd);
    gn_apply_k<<<dim3(NHW / 32, NC / 32, NB), t32>>>(x, gn_g, gn_b, gmean, grstd, xn);

    // 2) proj_in: h = xn @ pin + b   (fp32 out)
    hg<0>(xn, w16 + WT_PIN, h, nullptr, NTOK, ND, ND, ND, ND, ND, pin_b, nullptr, 0);

    // 3) self-attention
    ln_k<<<NTOK, 256>>>(h, ln1_g, ln1_b, hn);
    hg<1>(hn, w16 + WT_Q1, nullptr, q, NTOK, ND, ND, ND, ND, ND, nullptr, nullptr, 0, 0.125f);
    hg<1>(hn, w16 + WT_K1, nullptr, k, NTOK, ND, ND, ND, ND, ND, nullptr, nullptr, 0);
    hg<1>(hn, w16 + WT_V1, nullptr, v, NTOK, ND, ND, ND, ND, ND, nullptr, nullptr, 0);
    flash_attn_k<16, 1024, 1024><<<dim3(8, 64), 256, FA_SMEM>>>(q, k, v, ao);
    hg<0>(ao, w16 + WT_O1, h, nullptr, NTOK, ND, ND, ND, ND, ND, o1_b, h, 0);

    // 4) cross-attention
    ln_k<<<NTOK, 256>>>(h, ln2_g, ln2_b, hn);
    hg<1>(hn, w16 + WT_Q2, nullptr, q, NTOK, ND, ND, ND, ND, ND, nullptr, nullptr, 0, 0.125f);
    hg<1>(ctx16, w16 + WT_K2, nullptr, k, NB * NL, ND, NDC, NDC, ND, ND, nullptr, nullptr, 0);
    hg<1>(ctx16, w16 + WT_V2, nullptr, v, NB * NL, ND, NDC, NDC, ND, ND, nullptr, nullptr, 0);
    flash_attn_k<2, 77, 77><<<dim3(8, 64), 256, FA_SMEM>>>(q, k, v, ao);
    hg<0>(ao, w16 + WT_O2, h, nullptr, NTOK, ND, ND, ND, ND, ND, o2_b, h, 0);

    // 5) feed-forward
    ln_k<<<NTOK, 256>>>(h, ln3_g, ln3_b, hn);
    hg<1>(hn, w16 + WT_FF1, nullptr, ff, NTOK, NFF, ND, ND, NFF, NFF, ff1_b, nullptr, 1);
    hg<2>(ff, w16 + WT_FF2, h, h16, NTOK, ND, NFF, NFF, ND, ND, ff2_b, h, 0);

    // 6) proj_out + input residual
    hg<0>(h16, w16 + WT_POUT, po, nullptr, NTOK, NC, ND, ND, NC, NC, pout_b, nullptr, 0);
    out_add_k<<<dim3(NC / 32, NHW / 32, NB), t32>>>(po, x, out);
}